// round 5
// baseline (speedup 1.0000x reference)
#include <cuda_runtime.h>
#include <cstdint>
#include <math_constants.h>

// Problem constants
#define Bq 2
#define Sq 2048
#define Hq 1024
#define NHq 16
#define HDq 64
#define Mq (Bq * Sq)   // 4096
#define BKV 128
#define NI (Sq / BKV)  // 16

// ---------------------------------------------------------------------------
// Scratch (device globals — no allocation allowed)
// ---------------------------------------------------------------------------
__device__ float g_xln[(size_t)Mq * Hq];   // 16 MB
__device__ float g_q[(size_t)Mq * Hq];     // 16 MB  [B,NH,S,HD]  (pre-scaled 1/8)
__device__ float g_k[(size_t)Mq * Hq];     // 16 MB  [B,NH,S,HD]
__device__ float g_v[(size_t)Mq * Hq];     // 16 MB  [B,NH,HD,S] (transposed)
__device__ float g_ctx[(size_t)Mq * Hq];   // 16 MB  [B,S,H]

// ---------------------------------------------------------------------------
// Portable PTX helpers (sm_80-level — tcgen05 unavailable on compute_103 target)
// ---------------------------------------------------------------------------
__device__ __forceinline__ uint32_t smem_to_u32(const void* p) {
    uint32_t a;
    asm("{ .reg .u64 t; cvta.to.shared.u64 t, %1; cvt.u32.u64 %0, t; }" : "=r"(a) : "l"(p));
    return a;
}
__device__ __forceinline__ void cp_async16(uint32_t dst, const void* src) {
    asm volatile("cp.async.cg.shared.global [%0], [%1], 16;" :: "r"(dst), "l"(src));
}
__device__ __forceinline__ void cp_commit() {
    asm volatile("cp.async.commit_group;" ::: "memory");
}
__device__ __forceinline__ void cp_wait0() {
    asm volatile("cp.async.wait_group 0;" ::: "memory");
}
__device__ __forceinline__ void ldsm4(uint32_t& r0, uint32_t& r1, uint32_t& r2,
                                      uint32_t& r3, uint32_t addr) {
    asm volatile("ldmatrix.sync.aligned.m8n8.x4.shared.b16 {%0,%1,%2,%3}, [%4];"
                 : "=r"(r0), "=r"(r1), "=r"(r2), "=r"(r3) : "r"(addr));
}
__device__ __forceinline__ void mma_tf32(float* c, const uint32_t* a, const uint32_t* b) {
    asm volatile("mma.sync.aligned.m16n8k8.row.col.f32.tf32.tf32.f32 "
                 "{%0,%1,%2,%3}, {%4,%5,%6,%7}, {%8,%9}, {%0,%1,%2,%3};"
                 : "+f"(c[0]), "+f"(c[1]), "+f"(c[2]), "+f"(c[3])
                 : "r"(a[0]), "r"(a[1]), "r"(a[2]), "r"(a[3]), "r"(b[0]), "r"(b[1]));
}
__device__ __forceinline__ void cvt_tf32(uint32_t& x) {
    asm("cvt.rna.tf32.f32 %0, %0;" : "+r"(x));
}

// ---------------------------------------------------------------------------
// LayerNorm
// ---------------------------------------------------------------------------
__global__ __launch_bounds__(256) void ln_k(const float* __restrict__ x,
                                            const float* __restrict__ gamma,
                                            const float* __restrict__ beta,
                                            float* __restrict__ out) {
    const int row = blockIdx.x;
    const int tid = threadIdx.x;
    const float* xr = x + (size_t)row * Hq;

    float4 v = reinterpret_cast<const float4*>(xr)[tid];
    float s  = v.x + v.y + v.z + v.w;
    float ss = v.x * v.x + v.y * v.y + v.z * v.z + v.w * v.w;

    __shared__ float red[256];
    red[tid] = s; __syncthreads();
    for (int off = 128; off > 0; off >>= 1) {
        if (tid < off) red[tid] += red[tid + off];
        __syncthreads();
    }
    const float mean = red[0] * (1.0f / Hq);
    __syncthreads();
    red[tid] = ss; __syncthreads();
    for (int off = 128; off > 0; off >>= 1) {
        if (tid < off) red[tid] += red[tid + off];
        __syncthreads();
    }
    const float var  = red[0] * (1.0f / Hq) - mean * mean;
    const float rstd = rsqrtf(var + 1e-12f);

    float4 g = reinterpret_cast<const float4*>(gamma)[tid];
    float4 b = reinterpret_cast<const float4*>(beta)[tid];
    float4 o;
    o.x = (v.x - mean) * rstd * g.x + b.x;
    o.y = (v.y - mean) * rstd * g.y + b.y;
    o.z = (v.z - mean) * rstd * g.z + b.z;
    o.w = (v.w - mean) * rstd * g.w + b.w;
    reinterpret_cast<float4*>(out + (size_t)row * Hq)[tid] = o;
}

// ---------------------------------------------------------------------------
// tf32 mma.sync NT GEMM (projections + out-proj). Same as round-4 (passing).
// MODE 0: out-proj (+bias+residual); 1: Q/K proj -> [B,NH,S,HD] (*scale);
// MODE 4: V proj -> [B,NH,HD,S] transposed.
// ---------------------------------------------------------------------------
template <int BN, int MODE>
__global__ __launch_bounds__(256)
void wmma_k(const float* __restrict__ A, const float* __restrict__ B,
            const float* __restrict__ bias, const float* __restrict__ extra,
            float* __restrict__ C, int Kdim,
            long strideA, long strideB, long strideC, float scale) {
    constexpr int STAGES = 3;
    constexpr int ASZ = 128 * 128;
    constexpr int BSZ = BN * 128;
    constexpr int STG = ASZ + BSZ;
    constexpr int WGM = (BN == 128) ? 2 : 4;
    constexpr int WGN = 8 / WGM;
    constexpr int WM  = 128 / WGM;
    constexpr int WN  = BN / WGN;
    constexpr int MT  = WM / 16;
    constexpr int NT  = WN / 8;
    constexpr int NA4 = 4;
    constexpr int NB4 = BN / 32;

    extern __shared__ char smem[];
    const uint32_t sbase = smem_to_u32(smem);

    const int tid  = threadIdx.x;
    const int wid  = tid >> 5;
    const int lane = tid & 31;
    const int bz   = blockIdx.z;
    const int m0   = blockIdx.y * 128;
    const int n0   = blockIdx.x * BN;

    A += (size_t)bz * strideA;
    B += (size_t)bz * strideB;

    const int wm0 = (wid % WGM) * WM;
    const int wn0 = (wid / WGM) * WN;

    const int KT = Kdim >> 5;

    auto issue = [&](int kt) {
        const uint32_t abase = sbase + (uint32_t)(kt % STAGES) * STG;
        const float* Ak = A + (size_t)kt * 32;
#pragma unroll
        for (int i = 0; i < NA4; ++i) {
            const int idx = tid + i * 256, r = idx >> 3, c = idx & 7;
            const uint32_t dst = abase + r * 128 + ((c * 16) ^ ((r & 7) << 4));
            cp_async16(dst, Ak + (size_t)(m0 + r) * Kdim + c * 4);
        }
        const uint32_t bbase = abase + ASZ;
        const float* Bk = B + (size_t)kt * 32;
#pragma unroll
        for (int i = 0; i < NB4; ++i) {
            const int idx = tid + i * 256, r = idx >> 3, c = idx & 7;
            const uint32_t dst = bbase + r * 128 + ((c * 16) ^ ((r & 7) << 4));
            cp_async16(dst, Bk + (size_t)(n0 + r) * Kdim + c * 4);
        }
    };

    float acc[MT][NT][4];
#pragma unroll
    for (int i = 0; i < MT; ++i)
#pragma unroll
        for (int j = 0; j < NT; ++j)
#pragma unroll
            for (int e = 0; e < 4; ++e) acc[i][j][e] = 0.0f;

    const int a_ri = (lane & 7) + ((lane >> 3) & 1) * 8;
    const int a_ko = ((lane >> 4) & 1) * 16;
    const int b_ri = (lane & 7) + ((lane >> 4) & 1) * 8;
    const int b_ko = ((lane >> 3) & 1) * 16;

    for (int kt = 0; kt < STAGES - 1 && kt < KT; ++kt) {
        issue(kt);
        cp_commit();
    }

    for (int kt = 0; kt < KT; ++kt) {
        asm volatile("cp.async.wait_group %0;" :: "n"(STAGES - 2) : "memory");
        __syncthreads();
        if (kt + STAGES - 1 < KT) issue(kt + STAGES - 1);
        cp_commit();

        const uint32_t abase = sbase + (uint32_t)(kt % STAGES) * STG;
        const uint32_t bbase = abase + ASZ;
#pragma unroll
        for (int ks = 0; ks < 4; ++ks) {
            uint32_t af[MT][4], bf[NT][2];
#pragma unroll
            for (int mt = 0; mt < MT; ++mt) {
                const int row = wm0 + mt * 16 + a_ri;
                const int kb  = ks * 32 + a_ko;
                ldsm4(af[mt][0], af[mt][1], af[mt][2], af[mt][3],
                      abase + row * 128 + (kb ^ ((row & 7) << 4)));
            }
#pragma unroll
            for (int np = 0; np < NT / 2; ++np) {
                const int row = wn0 + np * 16 + b_ri;
                const int kb  = ks * 32 + b_ko;
                ldsm4(bf[2 * np][0], bf[2 * np][1], bf[2 * np + 1][0], bf[2 * np + 1][1],
                      bbase + row * 128 + (kb ^ ((row & 7) << 4)));
            }
#pragma unroll
            for (int mt = 0; mt < MT; ++mt)
#pragma unroll
                for (int e = 0; e < 4; ++e) cvt_tf32(af[mt][e]);
#pragma unroll
            for (int nt = 0; nt < NT; ++nt) {
                cvt_tf32(bf[nt][0]); cvt_tf32(bf[nt][1]);
            }
#pragma unroll
            for (int mt = 0; mt < MT; ++mt)
#pragma unroll
                for (int nt = 0; nt < NT; ++nt)
                    mma_tf32(acc[mt][nt], af[mt], bf[nt]);
        }
    }

    const int g = lane >> 2, tig = lane & 3;
#pragma unroll
    for (int mt = 0; mt < MT; ++mt) {
#pragma unroll
        for (int half = 0; half < 2; ++half) {
            const int m = m0 + wm0 + mt * 16 + g + half * 8;
#pragma unroll
            for (int nt = 0; nt < NT; ++nt) {
                const int n = n0 + wn0 + nt * 8 + 2 * tig;
                const float c0 = acc[mt][nt][half * 2 + 0];
                const float c1 = acc[mt][nt][half * 2 + 1];
                if (MODE == 0) {
                    const float2 bi = *reinterpret_cast<const float2*>(bias + n);
                    const float2 ex = *reinterpret_cast<const float2*>(extra + (size_t)m * Hq + n);
                    float2 o; o.x = c0 + bi.x + ex.x; o.y = c1 + bi.y + ex.y;
                    *reinterpret_cast<float2*>(C + (size_t)m * Hq + n) = o;
                } else if (MODE == 1) {
                    const float2 bi = *reinterpret_cast<const float2*>(bias + n);
                    const int bb = m >> 11, sI = m & (Sq - 1);
                    const int h = n >> 6, d = n & 63;
                    float2 o; o.x = (c0 + bi.x) * scale; o.y = (c1 + bi.y) * scale;
                    *reinterpret_cast<float2*>(
                        C + (((size_t)bb * NHq + h) * Sq + sI) * HDq + d) = o;
                } else {  // MODE 4: V transposed [B,NH,HD,S]
                    const int bb = m >> 11, sI = m & (Sq - 1);
                    const int h = n >> 6, d = n & 63;
                    float* dst = C + (((size_t)bb * NHq + h) * HDq + d) * Sq + sI;
                    dst[0]  = c0 + bias[n];
                    dst[Sq] = c1 + bias[n + 1];
                }
            }
        }
    }
}

// ---------------------------------------------------------------------------
// Fused flash attention: ctx = softmax(Q K^T + mask) V
//   Q: [B,NH,S,HD] pre-scaled;  K: [B,NH,S,HD];  V: [B,NH,HD,S] (transposed)
//   ctx: [B,S,H]
// Grid: (S/128, B*NH). 256 threads, 8 warps x 16 Q rows.
// smem: Q 32K | K 2x32K | V 2x32K | P 8x8K | mask 2x512
// ---------------------------------------------------------------------------
#define OFF_Q   0
#define OFF_K   32768
#define OFF_V   98304
#define OFF_P   163840
#define OFF_MK  229376
#define FLASH_SMEM 230400

__global__ __launch_bounds__(256)
void flash_k(const float* __restrict__ Qg, const float* __restrict__ Kg,
             const float* __restrict__ Vt, const float* __restrict__ mask,
             float* __restrict__ ctx) {
    extern __shared__ char smem[];
    const uint32_t sb = smem_to_u32(smem);

    const int tid  = threadIdx.x;
    const int wid  = tid >> 5;
    const int lane = tid & 31;
    const int m0   = blockIdx.x * 128;
    const int bz   = blockIdx.y;          // b*NH + h
    const int bb   = bz >> 4, hh = bz & 15;

    const float* Qb = Qg + ((size_t)bz * Sq + m0) * HDq;
    const float* Kb = Kg + (size_t)bz * Sq * HDq;
    const float* Vb = Vt + (size_t)bz * HDq * Sq;
    const float* mrow = mask + (size_t)bb * Sq;

    const uint32_t sQ = sb + OFF_Q;
    const uint32_t sP = sb + OFF_P + (uint32_t)wid * 8192;

    // ---- load Q tile: 128 rows x 64 floats -> 256 phys rows x 128B ----
#pragma unroll
    for (int i = 0; i < 8; ++i) {
        const int idx = tid + i * 256;
        const int r = idx >> 4, c = idx & 15;
        const int pr = 2 * r + (c >> 3);
        cp_async16(sQ + pr * 128 + (((c & 7) * 16) ^ ((pr & 7) << 4)),
                   Qb + (size_t)r * HDq + c * 4);
    }
    cp_commit();
    cp_wait0();
    __syncthreads();

    const int a_ri = (lane & 7) + ((lane >> 3) & 1) * 8;
    const int a_ko = ((lane >> 4) & 1) * 16;
    const int b_ri = (lane & 7) + ((lane >> 4) & 1) * 8;
    const int b_ko = ((lane >> 3) & 1) * 16;
    const int g    = lane >> 2, tig = lane & 3;

    // ---- hoist Q fragments (iteration-invariant): 8 k-steps x 4 regs ----
    uint32_t qf[8][4];
#pragma unroll
    for (int ks = 0; ks < 8; ++ks) {
        const int row = wid * 16 + a_ri;
        const int kb  = ks * 32 + a_ko;           // within 256B logical row
        const int pr  = 2 * row + (kb >> 7);
        ldsm4(qf[ks][0], qf[ks][1], qf[ks][2], qf[ks][3],
              sQ + pr * 128 + ((kb & 127) ^ ((pr & 7) << 4)));
        cvt_tf32(qf[ks][0]); cvt_tf32(qf[ks][1]);
        cvt_tf32(qf[ks][2]); cvt_tf32(qf[ks][3]);
    }

    auto issue_kv = [&](int it) {
        const uint32_t kB = sb + OFF_K + (uint32_t)(it & 1) * 32768;
        const uint32_t vB = sb + OFF_V + (uint32_t)(it & 1) * 32768;
        const float* Ks = Kb + (size_t)it * BKV * HDq;
#pragma unroll
        for (int i = 0; i < 8; ++i) {
            const int idx = tid + i * 256;
            const int r = idx >> 4, c = idx & 15;
            const int pr = 2 * r + (c >> 3);
            cp_async16(kB + pr * 128 + (((c & 7) * 16) ^ ((pr & 7) << 4)),
                       Ks + (size_t)r * HDq + c * 4);
        }
        const float* Vs = Vb + (size_t)it * BKV;  // V^T rows d (stride Sq)
#pragma unroll
        for (int i = 0; i < 8; ++i) {
            const int idx = tid + i * 256;
            const int d = idx >> 5, c = idx & 31;
            const int pr = 4 * d + (c >> 3);
            cp_async16(vB + pr * 128 + (((c & 7) * 16) ^ ((pr & 7) << 4)),
                       Vs + (size_t)d * Sq + c * 4);
        }
        if (tid < 128)
            *reinterpret_cast<float*>(smem + OFF_MK + (it & 1) * 512 + tid * 4) =
                mrow[it * BKV + tid];
    };

    issue_kv(0);
    cp_commit();

    float accO[8][4];
#pragma unroll
    for (int nt = 0; nt < 8; ++nt)
#pragma unroll
        for (int e = 0; e < 4; ++e) accO[nt][e] = 0.0f;
    float mst[2] = {-CUDART_INF_F, -CUDART_INF_F};
    float lst[2] = {0.0f, 0.0f};

    for (int it = 0; it < NI; ++it) {
        cp_wait0();
        __syncthreads();
        if (it + 1 < NI) {
            issue_kv(it + 1);
            cp_commit();
        }

        const uint32_t kB = sb + OFF_K + (uint32_t)(it & 1) * 32768;
        const uint32_t vB = sb + OFF_V + (uint32_t)(it & 1) * 32768;
        const char* mkB = smem + OFF_MK + (it & 1) * 512;

        // ---- S = Q K^T : warp tile 16 x 128 ----
        float accS[16][4];
#pragma unroll
        for (int nt = 0; nt < 16; ++nt)
#pragma unroll
            for (int e = 0; e < 4; ++e) accS[nt][e] = 0.0f;

#pragma unroll
        for (int ks = 0; ks < 8; ++ks) {
            const int kb = ks * 32 + b_ko;
            uint32_t bf[16][2];
#pragma unroll
            for (int np = 0; np < 8; ++np) {
                const int row = np * 16 + b_ri;
                const int pr  = 2 * row + (kb >> 7);
                ldsm4(bf[2 * np][0], bf[2 * np][1], bf[2 * np + 1][0], bf[2 * np + 1][1],
                      kB + pr * 128 + ((kb & 127) ^ ((pr & 7) << 4)));
            }
#pragma unroll
            for (int nt = 0; nt < 16; ++nt) {
                cvt_tf32(bf[nt][0]); cvt_tf32(bf[nt][1]);
            }
#pragma unroll
            for (int nt = 0; nt < 16; ++nt)
                mma_tf32(accS[nt], qf[ks], bf[nt]);
        }

        // ---- add mask ----
#pragma unroll
        for (int nt = 0; nt < 16; ++nt) {
            const float2 mk = *reinterpret_cast<const float2*>(mkB + (nt * 8 + 2 * tig) * 4);
            accS[nt][0] += mk.x; accS[nt][1] += mk.y;
            accS[nt][2] += mk.x; accS[nt][3] += mk.y;
        }

        // ---- online softmax (thread owns rows g, g+8; cols spread over quad) ----
        float rmax[2] = {-CUDART_INF_F, -CUDART_INF_F};
#pragma unroll
        for (int nt = 0; nt < 16; ++nt) {
            rmax[0] = fmaxf(rmax[0], fmaxf(accS[nt][0], accS[nt][1]));
            rmax[1] = fmaxf(rmax[1], fmaxf(accS[nt][2], accS[nt][3]));
        }
#pragma unroll
        for (int h = 0; h < 2; ++h) {
            rmax[h] = fmaxf(rmax[h], __shfl_xor_sync(0xffffffffu, rmax[h], 1));
            rmax[h] = fmaxf(rmax[h], __shfl_xor_sync(0xffffffffu, rmax[h], 2));
        }

        float scl[2], rsum[2] = {0.0f, 0.0f};
#pragma unroll
        for (int h = 0; h < 2; ++h) {
            const float mnew = fmaxf(mst[h], rmax[h]);
            scl[h] = __expf(mst[h] - mnew);
            mst[h] = mnew;
        }
#pragma unroll
        for (int nt = 0; nt < 16; ++nt) {
            accS[nt][0] = __expf(accS[nt][0] - mst[0]);
            accS[nt][1] = __expf(accS[nt][1] - mst[0]);
            accS[nt][2] = __expf(accS[nt][2] - mst[1]);
            accS[nt][3] = __expf(accS[nt][3] - mst[1]);
            rsum[0] += accS[nt][0] + accS[nt][1];
            rsum[1] += accS[nt][2] + accS[nt][3];
        }
#pragma unroll
        for (int h = 0; h < 2; ++h) {
            rsum[h] += __shfl_xor_sync(0xffffffffu, rsum[h], 1);
            rsum[h] += __shfl_xor_sync(0xffffffffu, rsum[h], 2);
            lst[h] = lst[h] * scl[h] + rsum[h];
        }
#pragma unroll
        for (int nt = 0; nt < 8; ++nt) {
            accO[nt][0] *= scl[0]; accO[nt][1] *= scl[0];
            accO[nt][2] *= scl[1]; accO[nt][3] *= scl[1];
        }

        // ---- write P to warp-private smem (16 rows x 128 floats) ----
#pragma unroll
        for (int nt = 0; nt < 16; ++nt) {
            const int c0 = nt * 8 + 2 * tig;
#pragma unroll
            for (int h = 0; h < 2; ++h) {
                const int r = g + 8 * h;
                const int pr = 4 * r + (c0 >> 5);
                const uint32_t off = pr * 128 + ((((c0 & 31) * 4)) ^ ((pr & 7) << 4));
                float2 o; o.x = accS[nt][2 * h]; o.y = accS[nt][2 * h + 1];
                asm volatile("st.shared.v2.f32 [%0], {%1, %2};"
                             :: "r"(sP + off), "f"(o.x), "f"(o.y) : "memory");
            }
        }
        __syncwarp();

        // ---- O += P V : A = P (16 x 128), B = V^T (64 x 128), both K-major ----
#pragma unroll
        for (int ks2 = 0; ks2 < 16; ++ks2) {
            uint32_t af[4];
            {
                const int kb = ks2 * 32 + a_ko;     // within 512B logical P row
                const int pr = 4 * a_ri + (kb >> 7);
                ldsm4(af[0], af[1], af[2], af[3],
                      sP + pr * 128 + ((kb & 127) ^ ((pr & 7) << 4)));
                cvt_tf32(af[0]); cvt_tf32(af[1]); cvt_tf32(af[2]); cvt_tf32(af[3]);
            }
            uint32_t bf[8][2];
            const int kbB = ks2 * 32 + b_ko;
#pragma unroll
            for (int np = 0; np < 4; ++np) {
                const int d  = np * 16 + b_ri;
                const int pr = 4 * d + (kbB >> 7);
                ldsm4(bf[2 * np][0], bf[2 * np][1], bf[2 * np + 1][0], bf[2 * np + 1][1],
                      vB + pr * 128 + ((kbB & 127) ^ ((pr & 7) << 4)));
            }
#pragma unroll
            for (int nt = 0; nt < 8; ++nt) {
                cvt_tf32(bf[nt][0]); cvt_tf32(bf[nt][1]);
            }
#pragma unroll
            for (int nt = 0; nt < 8; ++nt)
                mma_tf32(accO[nt], af, bf[nt]);
        }
    }

    // ---- epilogue: O / l -> ctx[B,S,H] ----
    const float inv0 = 1.0f / lst[0];
    const float inv1 = 1.0f / lst[1];
#pragma unroll
    for (int h = 0; h < 2; ++h) {
        const int sI = m0 + wid * 16 + g + 8 * h;
        float* crow = ctx + ((size_t)bb * Sq + sI) * Hq + hh * HDq;
        const float inv = h ? inv1 : inv0;
#pragma unroll
        for (int nt = 0; nt < 8; ++nt) {
            const int d = nt * 8 + 2 * tig;
            float2 o;
            o.x = accO[nt][2 * h + 0] * inv;
            o.y = accO[nt][2 * h + 1] * inv;
            *reinterpret_cast<float2*>(crow + d) = o;
        }
    }
}

// ---------------------------------------------------------------------------
// Launch
// ---------------------------------------------------------------------------
extern "C" void kernel_launch(void* const* d_in, const int* in_sizes, int n_in,
                              void* d_out, int out_size) {
    const float* hs   = (const float*)d_in[0];
    const float* mask = (const float*)d_in[1];
    const float* wq   = (const float*)d_in[2];
    const float* bq   = (const float*)d_in[3];
    const float* wk   = (const float*)d_in[4];
    const float* bk   = (const float*)d_in[5];
    const float* wv   = (const float*)d_in[6];
    const float* bv   = (const float*)d_in[7];
    const float* wo   = (const float*)d_in[8];
    const float* bo   = (const float*)d_in[9];
    const float* gam  = (const float*)d_in[10];
    const float* bet  = (const float*)d_in[11];
    float* out = (float*)d_out;

    float *xln, *q, *k, *v, *ctx;
    cudaGetSymbolAddress((void**)&xln, g_xln);
    cudaGetSymbolAddress((void**)&q,   g_q);
    cudaGetSymbolAddress((void**)&k,   g_k);
    cudaGetSymbolAddress((void**)&v,   g_v);
    cudaGetSymbolAddress((void**)&ctx, g_ctx);

    constexpr int SM128 = 3 * (128 * 128 + 128 * 128);  // 98304
    cudaFuncSetAttribute((const void*)wmma_k<128, 0>, cudaFuncAttributeMaxDynamicSharedMemorySize, SM128);
    cudaFuncSetAttribute((const void*)wmma_k<128, 1>, cudaFuncAttributeMaxDynamicSharedMemorySize, SM128);
    cudaFuncSetAttribute((const void*)wmma_k<128, 4>, cudaFuncAttributeMaxDynamicSharedMemorySize, SM128);
    cudaFuncSetAttribute((const void*)flash_k, cudaFuncAttributeMaxDynamicSharedMemorySize, FLASH_SMEM);

    // 1) LayerNorm
    ln_k<<<Mq, 256>>>(hs, gam, bet, xln);

    // 2) QKV projections. Q pre-scaled by 1/8; V written transposed.
    wmma_k<128, 1><<<dim3(Hq / 128, Mq / 128, 1), 256, SM128>>>(
        xln, wq, bq, nullptr, q, Hq, 0, 0, 0, 0.125f);
    wmma_k<128, 1><<<dim3(Hq / 128, Mq / 128, 1), 256, SM128>>>(
        xln, wk, bk, nullptr, k, Hq, 0, 0, 0, 1.0f);
    wmma_k<128, 4><<<dim3(Hq / 128, Mq / 128, 1), 256, SM128>>>(
        xln, wv, bv, nullptr, v, Hq, 0, 0, 0, 1.0f);

    // 3) fused attention -> ctx
    flash_k<<<dim3(Sq / 128, Bq * NHq), 256, FLASH_SMEM>>>(q, k, v, mask, ctx);

    // 4) out = ctx Wo^T + bo + residual
    wmma_k<128, 0><<<dim3(Hq / 128, Mq / 128, 1), 256, SM128>>>(
        ctx, wo, bo, hs, out, Hq, 0, 0, 0, 1.0f);
}

// round 6
// speedup vs baseline: 1.2525x; 1.2525x over previous
#include <cuda_runtime.h>
#include <cstdint>
#include <math_constants.h>

// Problem constants
#define Bq 2
#define Sq 2048
#define Hq 1024
#define NHq 16
#define HDq 64
#define Mq (Bq * Sq)   // 4096

// ---------------------------------------------------------------------------
// Scratch (device globals — no allocation allowed)
// ---------------------------------------------------------------------------
__device__ float g_xln[(size_t)Mq * Hq];               // 16 MB
__device__ float g_q[(size_t)Mq * Hq];                 // 16 MB  [B,NH,S,HD] (pre-scaled)
__device__ float g_k[(size_t)Mq * Hq];                 // 16 MB  [B,NH,S,HD]
__device__ float g_v[(size_t)Mq * Hq];                 // 16 MB  [B,NH,HD,S] (transposed)
__device__ float g_sc[(size_t)Bq * NHq * Sq * Sq];     // 512 MB scores (mask fused)
__device__ float g_ctx[(size_t)Mq * Hq];               // 16 MB  [B,S,H]

// ---------------------------------------------------------------------------
// Portable PTX helpers (sm_80-level — tcgen05 unavailable on compute_103 target)
// ---------------------------------------------------------------------------
__device__ __forceinline__ uint32_t smem_to_u32(const void* p) {
    uint32_t a;
    asm("{ .reg .u64 t; cvta.to.shared.u64 t, %1; cvt.u32.u64 %0, t; }" : "=r"(a) : "l"(p));
    return a;
}
__device__ __forceinline__ void cp_async16(uint32_t dst, const void* src) {
    asm volatile("cp.async.cg.shared.global [%0], [%1], 16;" :: "r"(dst), "l"(src));
}
__device__ __forceinline__ void cp_commit() {
    asm volatile("cp.async.commit_group;" ::: "memory");
}
__device__ __forceinline__ void cp_wait0() {
    asm volatile("cp.async.wait_group 0;" ::: "memory");
}
__device__ __forceinline__ void ldsm4(uint32_t& r0, uint32_t& r1, uint32_t& r2,
                                      uint32_t& r3, uint32_t addr) {
    asm volatile("ldmatrix.sync.aligned.m8n8.x4.shared.b16 {%0,%1,%2,%3}, [%4];"
                 : "=r"(r0), "=r"(r1), "=r"(r2), "=r"(r3) : "r"(addr));
}
__device__ __forceinline__ void mma_tf32(float* c, const uint32_t* a, const uint32_t* b) {
    asm volatile("mma.sync.aligned.m16n8k8.row.col.f32.tf32.tf32.f32 "
                 "{%0,%1,%2,%3}, {%4,%5,%6,%7}, {%8,%9}, {%0,%1,%2,%3};"
                 : "+f"(c[0]), "+f"(c[1]), "+f"(c[2]), "+f"(c[3])
                 : "r"(a[0]), "r"(a[1]), "r"(a[2]), "r"(a[3]), "r"(b[0]), "r"(b[1]));
}
__device__ __forceinline__ void cvt_tf32(uint32_t& x) {
    asm("cvt.rna.tf32.f32 %0, %0;" : "+r"(x));
}

// ---------------------------------------------------------------------------
// LayerNorm
// ---------------------------------------------------------------------------
__global__ __launch_bounds__(256) void ln_k(const float* __restrict__ x,
                                            const float* __restrict__ gamma,
                                            const float* __restrict__ beta,
                                            float* __restrict__ out) {
    const int row = blockIdx.x;
    const int tid = threadIdx.x;
    const float* xr = x + (size_t)row * Hq;

    float4 v = reinterpret_cast<const float4*>(xr)[tid];
    float s  = v.x + v.y + v.z + v.w;
    float ss = v.x * v.x + v.y * v.y + v.z * v.z + v.w * v.w;

    __shared__ float red[256];
    red[tid] = s; __syncthreads();
    for (int off = 128; off > 0; off >>= 1) {
        if (tid < off) red[tid] += red[tid + off];
        __syncthreads();
    }
    const float mean = red[0] * (1.0f / Hq);
    __syncthreads();
    red[tid] = ss; __syncthreads();
    for (int off = 128; off > 0; off >>= 1) {
        if (tid < off) red[tid] += red[tid + off];
        __syncthreads();
    }
    const float var  = red[0] * (1.0f / Hq) - mean * mean;
    const float rstd = rsqrtf(var + 1e-12f);

    float4 g = reinterpret_cast<const float4*>(gamma)[tid];
    float4 b = reinterpret_cast<const float4*>(beta)[tid];
    float4 o;
    o.x = (v.x - mean) * rstd * g.x + b.x;
    o.y = (v.y - mean) * rstd * g.y + b.y;
    o.z = (v.z - mean) * rstd * g.z + b.z;
    o.w = (v.w - mean) * rstd * g.w + b.w;
    reinterpret_cast<float4*>(out + (size_t)row * Hq)[tid] = o;
}

// ---------------------------------------------------------------------------
// tf32 mma.sync NT GEMM:  C_tile[128, 64] = A[M,K] * B[N,K]^T (both K-major)
// 8 warps as 4x2 grid of 32x32 warp tiles; 3-stage cp.async; 2 CTAs/SM.
// MODE 0: out-proj (+bias+residual)     -> [B*S, H]
// MODE 1: Q/K proj (+bias, *scale)      -> [B,NH,S,HD]
// MODE 2: scores (+mask)                -> sc + bz*S*S (row stride S)
// MODE 4: V proj (+bias)                -> [B,NH,HD,S] (transposed)
// ---------------------------------------------------------------------------
template <int MODE>
__global__ __launch_bounds__(256, 2)
void wmma_k(const float* __restrict__ A, const float* __restrict__ B,
            const float* __restrict__ bias, const float* __restrict__ extra,
            float* __restrict__ C, int Kdim,
            long strideA, long strideB, long strideC, float scale) {
    constexpr int STAGES = 3;
    constexpr int ASZ = 128 * 128;   // 16 KB: 128 rows x 32 floats
    constexpr int BSZ = 64 * 128;    // 8 KB
    constexpr int STG = ASZ + BSZ;
    constexpr int MT = 2, NT = 4;

    extern __shared__ char smem[];
    const uint32_t sbase = smem_to_u32(smem);

    const int tid  = threadIdx.x;
    const int wid  = tid >> 5;
    const int lane = tid & 31;
    const int bz   = blockIdx.z;
    const int m0   = blockIdx.y * 128;
    const int n0   = blockIdx.x * 64;

    A += (size_t)bz * strideA;
    B += (size_t)bz * strideB;

    const int wm0 = (wid & 3) * 32;   // 4 m-warps
    const int wn0 = (wid >> 2) * 32;  // 2 n-warps

    const int KT = Kdim >> 5;

    auto issue = [&](int kt) {
        const uint32_t abase = sbase + (uint32_t)(kt % STAGES) * STG;
        const float* Ak = A + (size_t)kt * 32;
#pragma unroll
        for (int i = 0; i < 4; ++i) {
            const int idx = tid + i * 256, r = idx >> 3, c = idx & 7;
            cp_async16(abase + r * 128 + ((c * 16) ^ ((r & 7) << 4)),
                       Ak + (size_t)(m0 + r) * Kdim + c * 4);
        }
        const uint32_t bbase = abase + ASZ;
        const float* Bk = B + (size_t)kt * 32;
#pragma unroll
        for (int i = 0; i < 2; ++i) {
            const int idx = tid + i * 256, r = idx >> 3, c = idx & 7;
            cp_async16(bbase + r * 128 + ((c * 16) ^ ((r & 7) << 4)),
                       Bk + (size_t)(n0 + r) * Kdim + c * 4);
        }
    };

    float acc[MT][NT][4];
#pragma unroll
    for (int i = 0; i < MT; ++i)
#pragma unroll
        for (int j = 0; j < NT; ++j)
#pragma unroll
            for (int e = 0; e < 4; ++e) acc[i][j][e] = 0.0f;

    const int a_ri = (lane & 7) + ((lane >> 3) & 1) * 8;
    const int a_ko = ((lane >> 4) & 1) * 16;
    const int b_ri = (lane & 7) + ((lane >> 4) & 1) * 8;
    const int b_ko = ((lane >> 3) & 1) * 16;

    for (int kt = 0; kt < STAGES - 1 && kt < KT; ++kt) {
        issue(kt);
        cp_commit();
    }

    for (int kt = 0; kt < KT; ++kt) {
        asm volatile("cp.async.wait_group %0;" :: "n"(STAGES - 2) : "memory");
        __syncthreads();
        if (kt + STAGES - 1 < KT) issue(kt + STAGES - 1);
        cp_commit();

        const uint32_t abase = sbase + (uint32_t)(kt % STAGES) * STG;
        const uint32_t bbase = abase + ASZ;
#pragma unroll
        for (int ks = 0; ks < 4; ++ks) {
            uint32_t af[MT][4], bf[NT][2];
#pragma unroll
            for (int mt = 0; mt < MT; ++mt) {
                const int row = wm0 + mt * 16 + a_ri;
                const int kb  = ks * 32 + a_ko;
                ldsm4(af[mt][0], af[mt][1], af[mt][2], af[mt][3],
                      abase + row * 128 + (kb ^ ((row & 7) << 4)));
            }
#pragma unroll
            for (int np = 0; np < NT / 2; ++np) {
                const int row = wn0 + np * 16 + b_ri;
                const int kb  = ks * 32 + b_ko;
                ldsm4(bf[2 * np][0], bf[2 * np][1], bf[2 * np + 1][0], bf[2 * np + 1][1],
                      bbase + row * 128 + (kb ^ ((row & 7) << 4)));
            }
#pragma unroll
            for (int mt = 0; mt < MT; ++mt)
#pragma unroll
                for (int e = 0; e < 4; ++e) cvt_tf32(af[mt][e]);
#pragma unroll
            for (int nt = 0; nt < NT; ++nt) {
                cvt_tf32(bf[nt][0]); cvt_tf32(bf[nt][1]);
            }
#pragma unroll
            for (int mt = 0; mt < MT; ++mt)
#pragma unroll
                for (int nt = 0; nt < NT; ++nt)
                    mma_tf32(acc[mt][nt], af[mt], bf[nt]);
        }
    }

    const int g = lane >> 2, tig = lane & 3;
#pragma unroll
    for (int mt = 0; mt < MT; ++mt) {
#pragma unroll
        for (int half = 0; half < 2; ++half) {
            const int m = m0 + wm0 + mt * 16 + g + half * 8;
#pragma unroll
            for (int nt = 0; nt < NT; ++nt) {
                const int n = n0 + wn0 + nt * 8 + 2 * tig;
                const float c0 = acc[mt][nt][half * 2 + 0];
                const float c1 = acc[mt][nt][half * 2 + 1];
                if (MODE == 0) {
                    const float2 bi = *reinterpret_cast<const float2*>(bias + n);
                    const float2 ex = *reinterpret_cast<const float2*>(extra + (size_t)m * Hq + n);
                    float2 o; o.x = c0 + bi.x + ex.x; o.y = c1 + bi.y + ex.y;
                    *reinterpret_cast<float2*>(C + (size_t)m * Hq + n) = o;
                } else if (MODE == 1) {
                    const float2 bi = *reinterpret_cast<const float2*>(bias + n);
                    const int bb = m >> 11, sI = m & (Sq - 1);
                    const int h = n >> 6, d = n & 63;
                    float2 o; o.x = (c0 + bi.x) * scale; o.y = (c1 + bi.y) * scale;
                    *reinterpret_cast<float2*>(
                        C + (((size_t)bb * NHq + h) * Sq + sI) * HDq + d) = o;
                } else if (MODE == 2) {
                    const int bb = bz / NHq;
                    const float2 mk = *reinterpret_cast<const float2*>(extra + (size_t)bb * Sq + n);
                    float2 o; o.x = c0 + mk.x; o.y = c1 + mk.y;
                    *reinterpret_cast<float2*>(C + (size_t)bz * strideC + (size_t)m * Sq + n) = o;
                } else {  // MODE 4: V transposed [B,NH,HD,S]
                    const int bb = m >> 11, sI = m & (Sq - 1);
                    const int h = n >> 6, d = n & 63;
                    float* dst = C + (((size_t)bb * NHq + h) * HDq + d) * Sq + sI;
                    dst[0]  = c0 + bias[n];
                    dst[Sq] = c1 + bias[n + 1];
                }
            }
        }
    }
}

// ---------------------------------------------------------------------------
// Fused online-softmax + PV:  ctx = softmax(S) V
//   S: [B*NH, Sq, Sq] fp32 (mask already added);  V: [B,NH,HD,S] transposed
// Grid: (Sq/128, B*NH), 256 threads, 8 warps x 16 rows; 32 iters of 64 KV cols.
// Key trick: S is ldsm'd directly into MMA A-fragment layout; softmax runs on
// the fragments in registers (quad shuffles for row stats) -> exp(S) fragments
// feed the PV MMA with NO smem round-trip.
// smem: S 2x32KB | V 2x16KB = 96 KB -> 2 CTAs/SM.
// ---------------------------------------------------------------------------
#define SPV_SMEM 98304

__global__ __launch_bounds__(256, 2)
void spv_k(const float* __restrict__ Sg, const float* __restrict__ Vt,
           float* __restrict__ ctx) {
    extern __shared__ char smem[];
    const uint32_t sb = smem_to_u32(smem);

    const int tid  = threadIdx.x;
    const int wid  = tid >> 5;
    const int lane = tid & 31;
    const int m0   = blockIdx.x * 128;
    const int bz   = blockIdx.y;
    const int bb   = bz >> 4, hh = bz & 15;

    const float* Sb = Sg + (size_t)bz * Sq * Sq + (size_t)m0 * Sq;
    const float* Vb = Vt + (size_t)bz * HDq * Sq;

    auto issue = [&](int it) {
        const uint32_t sS = sb + (uint32_t)(it & 1) * 32768;
        // S tile: 128 rows x 64 floats (256B logical -> 2 phys rows of 128B)
#pragma unroll
        for (int i = 0; i < 8; ++i) {
            const int idx = tid + i * 256;
            const int r = idx >> 4, c4 = idx & 15;
            const int pr = 2 * r + (c4 >> 3);
            cp_async16(sS + pr * 128 + (((c4 & 7) * 16) ^ ((pr & 7) << 4)),
                       Sb + (size_t)r * Sq + it * 64 + c4 * 4);
        }
        const uint32_t sV = sb + 65536 + (uint32_t)(it & 1) * 16384;
        // V tile: 64 d-rows x 64 floats
#pragma unroll
        for (int i = 0; i < 4; ++i) {
            const int idx = tid + i * 256;
            const int d = idx >> 4, c4 = idx & 15;
            const int pr = 2 * d + (c4 >> 3);
            cp_async16(sV + pr * 128 + (((c4 & 7) * 16) ^ ((pr & 7) << 4)),
                       Vb + (size_t)d * Sq + it * 64 + c4 * 4);
        }
    };

    issue(0);
    cp_commit();

    const int a_ri = (lane & 7) + ((lane >> 3) & 1) * 8;
    const int a_ko = ((lane >> 4) & 1) * 16;
    const int b_ri = (lane & 7) + ((lane >> 4) & 1) * 8;
    const int b_ko = ((lane >> 3) & 1) * 16;
    const int g    = lane >> 2, tig = lane & 3;

    float accO[8][4];
#pragma unroll
    for (int nt = 0; nt < 8; ++nt)
#pragma unroll
        for (int e = 0; e < 4; ++e) accO[nt][e] = 0.0f;
    float mst[2] = {-CUDART_INF_F, -CUDART_INF_F};
    float lst[2] = {0.0f, 0.0f};

    for (int it = 0; it < 32; ++it) {
        cp_wait0();
        __syncthreads();
        if (it + 1 < 32) {
            issue(it + 1);
            cp_commit();
        }

        const uint32_t sS = sb + (uint32_t)(it & 1) * 32768;
        const uint32_t sV = sb + 65536 + (uint32_t)(it & 1) * 16384;

        // ---- ldsm S directly as A-fragments (rows wid*16..+16, cols 64) ----
        uint32_t sf[8][4];
#pragma unroll
        for (int ks = 0; ks < 8; ++ks) {
            const int row = wid * 16 + a_ri;
            const int kb  = ks * 32 + a_ko;
            const int pr  = 2 * row + (kb >> 7);
            ldsm4(sf[ks][0], sf[ks][1], sf[ks][2], sf[ks][3],
                  sS + pr * 128 + ((kb & 127) ^ ((pr & 7) << 4)));
        }
        // A-fragment layout: [0]=(g,c), [1]=(g+8,c), [2]=(g,c+4), [3]=(g+8,c+4)
        float aS[8][4];
#pragma unroll
        for (int ks = 0; ks < 8; ++ks)
#pragma unroll
            for (int e = 0; e < 4; ++e) aS[ks][e] = __uint_as_float(sf[ks][e]);

        // ---- online softmax over this 64-col chunk ----
        float rmax[2] = {-CUDART_INF_F, -CUDART_INF_F};
#pragma unroll
        for (int ks = 0; ks < 8; ++ks) {
            rmax[0] = fmaxf(rmax[0], fmaxf(aS[ks][0], aS[ks][2]));
            rmax[1] = fmaxf(rmax[1], fmaxf(aS[ks][1], aS[ks][3]));
        }
#pragma unroll
        for (int h = 0; h < 2; ++h) {
            rmax[h] = fmaxf(rmax[h], __shfl_xor_sync(0xffffffffu, rmax[h], 1));
            rmax[h] = fmaxf(rmax[h], __shfl_xor_sync(0xffffffffu, rmax[h], 2));
        }
        float scl[2], rsum[2] = {0.0f, 0.0f};
#pragma unroll
        for (int h = 0; h < 2; ++h) {
            const float mnew = fmaxf(mst[h], rmax[h]);
            scl[h] = __expf(mst[h] - mnew);
            mst[h] = mnew;
        }
#pragma unroll
        for (int ks = 0; ks < 8; ++ks) {
            aS[ks][0] = __expf(aS[ks][0] - mst[0]);
            aS[ks][2] = __expf(aS[ks][2] - mst[0]);
            aS[ks][1] = __expf(aS[ks][1] - mst[1]);
            aS[ks][3] = __expf(aS[ks][3] - mst[1]);
            rsum[0] += aS[ks][0] + aS[ks][2];
            rsum[1] += aS[ks][1] + aS[ks][3];
        }
#pragma unroll
        for (int h = 0; h < 2; ++h) {
            rsum[h] += __shfl_xor_sync(0xffffffffu, rsum[h], 1);
            rsum[h] += __shfl_xor_sync(0xffffffffu, rsum[h], 2);
            lst[h] = lst[h] * scl[h] + rsum[h];
        }
#pragma unroll
        for (int nt = 0; nt < 8; ++nt) {
            accO[nt][0] *= scl[0]; accO[nt][1] *= scl[0];
            accO[nt][2] *= scl[1]; accO[nt][3] *= scl[1];
        }

        // ---- exp(S) fragments are already A-layout: convert and MMA ----
#pragma unroll
        for (int ks = 0; ks < 8; ++ks) {
            uint32_t af[4];
#pragma unroll
            for (int e = 0; e < 4; ++e) {
                af[e] = __float_as_uint(aS[ks][e]);
                cvt_tf32(af[e]);
            }
            uint32_t bf[8][2];
            const int kb = ks * 32 + b_ko;
#pragma unroll
            for (int np = 0; np < 4; ++np) {
                const int row = np * 16 + b_ri;
                const int pr  = 2 * row + (kb >> 7);
                ldsm4(bf[2 * np][0], bf[2 * np][1], bf[2 * np + 1][0], bf[2 * np + 1][1],
                      sV + pr * 128 + ((kb & 127) ^ ((pr & 7) << 4)));
            }
#pragma unroll
            for (int nt = 0; nt < 8; ++nt) {
                cvt_tf32(bf[nt][0]); cvt_tf32(bf[nt][1]);
            }
#pragma unroll
            for (int nt = 0; nt < 8; ++nt)
                mma_tf32(accO[nt], af, bf[nt]);
        }
    }

    // ---- epilogue: O / l -> ctx[B,S,H] ----
#pragma unroll
    for (int h = 0; h < 2; ++h) {
        const int sI = m0 + wid * 16 + g + 8 * h;
        float* crow = ctx + ((size_t)bb * Sq + sI) * Hq + hh * HDq;
        const float inv = 1.0f / lst[h];
#pragma unroll
        for (int nt = 0; nt < 8; ++nt) {
            const int d = nt * 8 + 2 * tig;
            float2 o;
            o.x = accO[nt][2 * h + 0] * inv;
            o.y = accO[nt][2 * h + 1] * inv;
            *reinterpret_cast<float2*>(crow + d) = o;
        }
    }
}

// ---------------------------------------------------------------------------
// Launch
// ---------------------------------------------------------------------------
extern "C" void kernel_launch(void* const* d_in, const int* in_sizes, int n_in,
                              void* d_out, int out_size) {
    const float* hs   = (const float*)d_in[0];
    const float* mask = (const float*)d_in[1];
    const float* wq   = (const float*)d_in[2];
    const float* bq   = (const float*)d_in[3];
    const float* wk   = (const float*)d_in[4];
    const float* bk   = (const float*)d_in[5];
    const float* wv   = (const float*)d_in[6];
    const float* bv   = (const float*)d_in[7];
    const float* wo   = (const float*)d_in[8];
    const float* bo   = (const float*)d_in[9];
    const float* gam  = (const float*)d_in[10];
    const float* bet  = (const float*)d_in[11];
    float* out = (float*)d_out;

    float *xln, *q, *k, *v, *sc, *ctx;
    cudaGetSymbolAddress((void**)&xln, g_xln);
    cudaGetSymbolAddress((void**)&q,   g_q);
    cudaGetSymbolAddress((void**)&k,   g_k);
    cudaGetSymbolAddress((void**)&v,   g_v);
    cudaGetSymbolAddress((void**)&sc,  g_sc);
    cudaGetSymbolAddress((void**)&ctx, g_ctx);

    constexpr int SMW = 3 * (128 * 128 + 64 * 128);  // 73728
    cudaFuncSetAttribute((const void*)wmma_k<0>, cudaFuncAttributeMaxDynamicSharedMemorySize, SMW);
    cudaFuncSetAttribute((const void*)wmma_k<1>, cudaFuncAttributeMaxDynamicSharedMemorySize, SMW);
    cudaFuncSetAttribute((const void*)wmma_k<2>, cudaFuncAttributeMaxDynamicSharedMemorySize, SMW);
    cudaFuncSetAttribute((const void*)wmma_k<4>, cudaFuncAttributeMaxDynamicSharedMemorySize, SMW);
    cudaFuncSetAttribute((const void*)spv_k, cudaFuncAttributeMaxDynamicSharedMemorySize, SPV_SMEM);

    // 1) LayerNorm
    ln_k<<<Mq, 256>>>(hs, gam, bet, xln);

    // 2) QKV projections. Q pre-scaled by 1/8; V written transposed.
    wmma_k<1><<<dim3(Hq / 64, Mq / 128, 1), 256, SMW>>>(
        xln, wq, bq, nullptr, q, Hq, 0, 0, 0, 0.125f);
    wmma_k<1><<<dim3(Hq / 64, Mq / 128, 1), 256, SMW>>>(
        xln, wk, bk, nullptr, k, Hq, 0, 0, 0, 1.0f);
    wmma_k<4><<<dim3(Hq / 64, Mq / 128, 1), 256, SMW>>>(
        xln, wv, bv, nullptr, v, Hq, 0, 0, 0, 1.0f);

    // 3) scores = Q K^T + mask, batched over B*NH=32, K=64
    wmma_k<2><<<dim3(Sq / 64, Sq / 128, Bq * NHq), 256, SMW>>>(
        q, k, nullptr, mask, sc, HDq,
        (long)Sq * HDq, (long)Sq * HDq, (long)Sq * Sq, 1.0f);

    // 4) fused online-softmax + PV -> ctx
    spv_k<<<dim3(Sq / 128, Bq * NHq), 256, SPV_SMEM>>>(sc, v, ctx);

    // 5) out = ctx Wo^T + bo + residual
    wmma_k<0><<<dim3(Hq / 64, Mq / 128, 1), 256, SMW>>>(
        ctx, wo, bo, hs, out, Hq, 0, 0, 0, 1.0f);
}

// round 7
// speedup vs baseline: 2.1089x; 1.6838x over previous
#include <cuda_runtime.h>
#include <cuda_bf16.h>
#include <cstdint>
#include <math_constants.h>

// Problem constants
#define Bq 2
#define Sq 2048
#define Hq 1024
#define NHq 16
#define HDq 64
#define Mq (Bq * Sq)   // 4096

// ---------------------------------------------------------------------------
// Scratch (device globals — no allocation allowed). All intermediates bf16.
// ---------------------------------------------------------------------------
__device__ __nv_bfloat16 g_xln[(size_t)Mq * Hq];                 // 8 MB
__device__ __nv_bfloat16 g_wq[(size_t)Hq * Hq];                  // 2 MB
__device__ __nv_bfloat16 g_wk[(size_t)Hq * Hq];
__device__ __nv_bfloat16 g_wv[(size_t)Hq * Hq];
__device__ __nv_bfloat16 g_wo[(size_t)Hq * Hq];
__device__ __nv_bfloat16 g_q[(size_t)Mq * Hq];                   // 8 MB [B,NH,S,HD] (pre-scaled)
__device__ __nv_bfloat16 g_k[(size_t)Mq * Hq];                   // 8 MB [B,NH,S,HD]
__device__ __nv_bfloat16 g_v[(size_t)Mq * Hq];                   // 8 MB [B,NH,HD,S] (transposed)
__device__ __nv_bfloat16 g_sc[(size_t)Bq * NHq * Sq * Sq];       // 256 MB scores (mask fused)
__device__ __nv_bfloat16 g_ctx[(size_t)Mq * Hq];                 // 8 MB [B,S,H]

// ---------------------------------------------------------------------------
// PTX helpers (sm_80-level — tcgen05 unavailable on compute_103 target)
// ---------------------------------------------------------------------------
__device__ __forceinline__ uint32_t smem_to_u32(const void* p) {
    uint32_t a;
    asm("{ .reg .u64 t; cvta.to.shared.u64 t, %1; cvt.u32.u64 %0, t; }" : "=r"(a) : "l"(p));
    return a;
}
__device__ __forceinline__ void cp_async16(uint32_t dst, const void* src) {
    asm volatile("cp.async.cg.shared.global [%0], [%1], 16;" :: "r"(dst), "l"(src));
}
__device__ __forceinline__ void cp_commit() {
    asm volatile("cp.async.commit_group;" ::: "memory");
}
__device__ __forceinline__ void ldsm4(uint32_t& r0, uint32_t& r1, uint32_t& r2,
                                      uint32_t& r3, uint32_t addr) {
    asm volatile("ldmatrix.sync.aligned.m8n8.x4.shared.b16 {%0,%1,%2,%3}, [%4];"
                 : "=r"(r0), "=r"(r1), "=r"(r2), "=r"(r3) : "r"(addr));
}
// m16n8k16 bf16 MMA, fp32 accumulate
__device__ __forceinline__ void mma_bf16(float* c, const uint32_t* a, const uint32_t* b) {
    asm volatile("mma.sync.aligned.m16n8k16.row.col.f32.bf16.bf16.f32 "
                 "{%0,%1,%2,%3}, {%4,%5,%6,%7}, {%8,%9}, {%0,%1,%2,%3};"
                 : "+f"(c[0]), "+f"(c[1]), "+f"(c[2]), "+f"(c[3])
                 : "r"(a[0]), "r"(a[1]), "r"(a[2]), "r"(a[3]), "r"(b[0]), "r"(b[1]));
}

// ---------------------------------------------------------------------------
// LayerNorm: fp32 in -> bf16 out
// ---------------------------------------------------------------------------
__global__ __launch_bounds__(256) void ln_k(const float* __restrict__ x,
                                            const float* __restrict__ gamma,
                                            const float* __restrict__ beta,
                                            __nv_bfloat16* __restrict__ out) {
    const int row = blockIdx.x;
    const int tid = threadIdx.x;
    const float* xr = x + (size_t)row * Hq;

    float4 v = reinterpret_cast<const float4*>(xr)[tid];
    float s  = v.x + v.y + v.z + v.w;
    float ss = v.x * v.x + v.y * v.y + v.z * v.z + v.w * v.w;

    __shared__ float red[256];
    red[tid] = s; __syncthreads();
    for (int off = 128; off > 0; off >>= 1) {
        if (tid < off) red[tid] += red[tid + off];
        __syncthreads();
    }
    const float mean = red[0] * (1.0f / Hq);
    __syncthreads();
    red[tid] = ss; __syncthreads();
    for (int off = 128; off > 0; off >>= 1) {
        if (tid < off) red[tid] += red[tid + off];
        __syncthreads();
    }
    const float var  = red[0] * (1.0f / Hq) - mean * mean;
    const float rstd = rsqrtf(var + 1e-12f);

    float4 g = reinterpret_cast<const float4*>(gamma)[tid];
    float4 b = reinterpret_cast<const float4*>(beta)[tid];
    __nv_bfloat162* orow = reinterpret_cast<__nv_bfloat162*>(out + (size_t)row * Hq);
    orow[2 * tid]     = __floats2bfloat162_rn((v.x - mean) * rstd * g.x + b.x,
                                              (v.y - mean) * rstd * g.y + b.y);
    orow[2 * tid + 1] = __floats2bfloat162_rn((v.z - mean) * rstd * g.z + b.z,
                                              (v.w - mean) * rstd * g.w + b.w);
}

// ---------------------------------------------------------------------------
// fp32 -> bf16 weight conversion
// ---------------------------------------------------------------------------
__global__ __launch_bounds__(256) void cvt_k(const float4* __restrict__ src,
                                             __nv_bfloat162* __restrict__ dst, int n4) {
    const int i = blockIdx.x * 256 + threadIdx.x;
    if (i < n4) {
        float4 v = src[i];
        dst[2 * i]     = __floats2bfloat162_rn(v.x, v.y);
        dst[2 * i + 1] = __floats2bfloat162_rn(v.z, v.w);
    }
}

// ---------------------------------------------------------------------------
// bf16 mma.sync NT GEMM:  C_tile[128, 64] = A[M,K] * B[N,K]^T (both K-major)
// k-chunks of 64 bf16 (128B rows), 3-stage cp.async, 8 warps as 4x2 of 32x32.
// MODE 0: out-proj (+bias+residual)  -> fp32 [B*S, H]
// MODE 1: Q/K proj (+bias, *scale)   -> bf16 [B,NH,S,HD]
// MODE 2: scores (+mask)             -> bf16 sc + bz*S*S
// MODE 4: V proj (+bias)             -> bf16 [B,NH,HD,S] (transposed)
// ---------------------------------------------------------------------------
template <int MODE>
__global__ __launch_bounds__(256, 2)
void wmma_k(const __nv_bfloat16* __restrict__ A, const __nv_bfloat16* __restrict__ B,
            const float* __restrict__ bias, const float* __restrict__ extra,
            void* __restrict__ Cv, int Kdim,
            long strideA, long strideB, long strideC, float scale) {
    constexpr int STAGES = 3;
    constexpr int ASZ = 128 * 128;   // 16 KB: 128 rows x 64 bf16
    constexpr int BSZ = 64 * 128;    // 8 KB
    constexpr int STG = ASZ + BSZ;
    constexpr int MT = 2, NT = 4;

    extern __shared__ char smem[];
    const uint32_t sbase = smem_to_u32(smem);

    const int tid  = threadIdx.x;
    const int wid  = tid >> 5;
    const int lane = tid & 31;
    const int bz   = blockIdx.z;
    const int m0   = blockIdx.y * 128;
    const int n0   = blockIdx.x * 64;

    A += (size_t)bz * strideA;
    B += (size_t)bz * strideB;

    const int wm0 = (wid & 3) * 32;
    const int wn0 = (wid >> 2) * 32;

    const int KT = Kdim >> 6;   // 64 bf16 per chunk

    auto issue = [&](int kt) {
        const uint32_t abase = sbase + (uint32_t)(kt % STAGES) * STG;
        const __nv_bfloat16* Ak = A + (size_t)kt * 64;
#pragma unroll
        for (int i = 0; i < 4; ++i) {
            const int idx = tid + i * 256, r = idx >> 3, c = idx & 7;
            cp_async16(abase + r * 128 + ((c * 16) ^ ((r & 7) << 4)),
                       Ak + (size_t)(m0 + r) * Kdim + c * 8);
        }
        const uint32_t bbase = abase + ASZ;
        const __nv_bfloat16* Bk = B + (size_t)kt * 64;
#pragma unroll
        for (int i = 0; i < 2; ++i) {
            const int idx = tid + i * 256, r = idx >> 3, c = idx & 7;
            cp_async16(bbase + r * 128 + ((c * 16) ^ ((r & 7) << 4)),
                       Bk + (size_t)(n0 + r) * Kdim + c * 8);
        }
    };

    float acc[MT][NT][4];
#pragma unroll
    for (int i = 0; i < MT; ++i)
#pragma unroll
        for (int j = 0; j < NT; ++j)
#pragma unroll
            for (int e = 0; e < 4; ++e) acc[i][j][e] = 0.0f;

    // ldsm lane decomposition (bf16 m16n8k16 fragments)
    const int mat = lane >> 3, mr = lane & 7;
    const int aro = (mat & 1) * 8 + mr;    // A: row offset, k16-half = mat>>1
    const int ako = (mat >> 1) * 16;
    const int bro = (mat >> 1) * 8 + mr;   // B: row offset, k16-half = mat&1
    const int bko = (mat & 1) * 16;

    for (int kt = 0; kt < STAGES - 1; ++kt) {
        if (kt < KT) issue(kt);
        cp_commit();
    }

    for (int kt = 0; kt < KT; ++kt) {
        asm volatile("cp.async.wait_group %0;" :: "n"(STAGES - 2) : "memory");
        __syncthreads();
        if (kt + STAGES - 1 < KT) issue(kt + STAGES - 1);
        cp_commit();

        const uint32_t abase = sbase + (uint32_t)(kt % STAGES) * STG;
        const uint32_t bbase = abase + ASZ;
#pragma unroll
        for (int ks = 0; ks < 4; ++ks) {
            uint32_t af[MT][4], bf[NT][2];
#pragma unroll
            for (int mt = 0; mt < MT; ++mt) {
                const int row = wm0 + mt * 16 + aro;
                const int kb  = ks * 32 + ako;
                ldsm4(af[mt][0], af[mt][1], af[mt][2], af[mt][3],
                      abase + row * 128 + (kb ^ ((row & 7) << 4)));
            }
#pragma unroll
            for (int np = 0; np < NT / 2; ++np) {
                const int row = wn0 + np * 16 + bro;
                const int kb  = ks * 32 + bko;
                ldsm4(bf[2 * np][0], bf[2 * np][1], bf[2 * np + 1][0], bf[2 * np + 1][1],
                      bbase + row * 128 + (kb ^ ((row & 7) << 4)));
            }
#pragma unroll
            for (int mt = 0; mt < MT; ++mt)
#pragma unroll
                for (int nt = 0; nt < NT; ++nt)
                    mma_bf16(acc[mt][nt], af[mt], bf[nt]);
        }
    }

    const int g = lane >> 2, tig = lane & 3;
#pragma unroll
    for (int mt = 0; mt < MT; ++mt) {
#pragma unroll
        for (int half = 0; half < 2; ++half) {
            const int m = m0 + wm0 + mt * 16 + g + half * 8;
#pragma unroll
            for (int nt = 0; nt < NT; ++nt) {
                const int n = n0 + wn0 + nt * 8 + 2 * tig;
                const float c0 = acc[mt][nt][half * 2 + 0];
                const float c1 = acc[mt][nt][half * 2 + 1];
                if (MODE == 0) {
                    float* C = (float*)Cv;
                    const float2 bi = *reinterpret_cast<const float2*>(bias + n);
                    const float2 ex = *reinterpret_cast<const float2*>(extra + (size_t)m * Hq + n);
                    float2 o; o.x = c0 + bi.x + ex.x; o.y = c1 + bi.y + ex.y;
                    *reinterpret_cast<float2*>(C + (size_t)m * Hq + n) = o;
                } else if (MODE == 1) {
                    __nv_bfloat16* C = (__nv_bfloat16*)Cv;
                    const float2 bi = *reinterpret_cast<const float2*>(bias + n);
                    const int bb = m >> 11, sI = m & (Sq - 1);
                    const int h = n >> 6, d = n & 63;
                    *reinterpret_cast<__nv_bfloat162*>(
                        C + (((size_t)bb * NHq + h) * Sq + sI) * HDq + d) =
                        __floats2bfloat162_rn((c0 + bi.x) * scale, (c1 + bi.y) * scale);
                } else if (MODE == 2) {
                    __nv_bfloat16* C = (__nv_bfloat16*)Cv;
                    const int bb = bz / NHq;
                    const float2 mk = *reinterpret_cast<const float2*>(extra + (size_t)bb * Sq + n);
                    *reinterpret_cast<__nv_bfloat162*>(
                        C + (size_t)bz * strideC + (size_t)m * Sq + n) =
                        __floats2bfloat162_rn(c0 + mk.x, c1 + mk.y);
                } else {  // MODE 4: V transposed [B,NH,HD,S]
                    __nv_bfloat16* C = (__nv_bfloat16*)Cv;
                    const int bb = m >> 11, sI = m & (Sq - 1);
                    const int h = n >> 6, d = n & 63;
                    __nv_bfloat16* dst = C + (((size_t)bb * NHq + h) * HDq + d) * Sq + sI;
                    dst[0]  = __float2bfloat16(c0 + bias[n]);
                    dst[Sq] = __float2bfloat16(c1 + bias[n + 1]);
                }
            }
        }
    }
}

// ---------------------------------------------------------------------------
// Fused online-softmax + PV (bf16):  ctx = softmax(S) V
//   S: [B*NH, Sq, Sq] bf16 (mask fused);  V: [B,NH,HD,S] bf16 transposed
// Grid (Sq/128, B*NH), 256 thr, 8 warps x 16 rows; 16 iters of 128 KV cols.
// S ldsm'd directly into bf16 A-fragment layout; softmax in fp32 on unpacked
// fragments; exp repacked to bf16 -> PV MMA with no smem round-trip.
// smem: S 2x32KB | V 2x16KB = 96 KB
// ---------------------------------------------------------------------------
#define SPV_SMEM 98304

__global__ __launch_bounds__(256, 2)
void spv_k(const __nv_bfloat16* __restrict__ Sg, const __nv_bfloat16* __restrict__ Vt,
           __nv_bfloat16* __restrict__ ctx) {
    extern __shared__ char smem[];
    const uint32_t sb = smem_to_u32(smem);

    const int tid  = threadIdx.x;
    const int wid  = tid >> 5;
    const int lane = tid & 31;
    const int m0   = blockIdx.x * 128;
    const int bz   = blockIdx.y;
    const int bb   = bz >> 4, hh = bz & 15;

    const __nv_bfloat16* Sb = Sg + (size_t)bz * Sq * Sq + (size_t)m0 * Sq;
    const __nv_bfloat16* Vb = Vt + (size_t)bz * HDq * Sq;

    auto issue = [&](int it) {
        const uint32_t sS = sb + (uint32_t)(it & 1) * 32768;
        // S tile: 128 rows x 128 bf16 (256B logical -> 2 phys rows x 128B)
#pragma unroll
        for (int i = 0; i < 8; ++i) {
            const int idx = tid + i * 256;
            const int r = idx >> 4, c = idx & 15;
            const int pr = 2 * r + (c >> 3);
            cp_async16(sS + pr * 128 + (((c & 7) * 16) ^ ((pr & 7) << 4)),
                       Sb + (size_t)r * Sq + it * 128 + c * 8);
        }
        const uint32_t sV = sb + 65536 + (uint32_t)(it & 1) * 16384;
        // V tile: 64 d-rows x 128 bf16
#pragma unroll
        for (int i = 0; i < 4; ++i) {
            const int idx = tid + i * 256;
            const int d = idx >> 4, c = idx & 15;
            const int pr = 2 * d + (c >> 3);
            cp_async16(sV + pr * 128 + (((c & 7) * 16) ^ ((pr & 7) << 4)),
                       Vb + (size_t)d * Sq + it * 128 + c * 8);
        }
    };

    issue(0);
    cp_commit();

    const int mat = lane >> 3, mr = lane & 7;
    const int aro = (mat & 1) * 8 + mr;
    const int ako = (mat >> 1) * 16;
    const int bro = (mat >> 1) * 8 + mr;
    const int bko = (mat & 1) * 16;
    const int g   = lane >> 2, tig = lane & 3;

    float accO[8][4];
#pragma unroll
    for (int nt = 0; nt < 8; ++nt)
#pragma unroll
        for (int e = 0; e < 4; ++e) accO[nt][e] = 0.0f;
    float mst[2] = {-CUDART_INF_F, -CUDART_INF_F};
    float lst[2] = {0.0f, 0.0f};

    for (int it = 0; it < 16; ++it) {
        asm volatile("cp.async.wait_group 0;" ::: "memory");
        __syncthreads();
        if (it + 1 < 16) {
            issue(it + 1);
            cp_commit();
        }

        const uint32_t sS = sb + (uint32_t)(it & 1) * 32768;
        const uint32_t sV = sb + 65536 + (uint32_t)(it & 1) * 16384;

        // ---- ldsm S as bf16 A-fragments; unpack to fp32 ----
        // reg 0,2 -> row g ; reg 1,3 -> row g+8
        uint32_t sf[8][4];
#pragma unroll
        for (int ks = 0; ks < 8; ++ks) {
            const int row = wid * 16 + aro;
            const int kb  = ks * 32 + ako;
            const int pr  = 2 * row + (kb >> 7);
            ldsm4(sf[ks][0], sf[ks][1], sf[ks][2], sf[ks][3],
                  sS + pr * 128 + ((kb & 127) ^ ((pr & 7) << 4)));
        }
        float e0[8][2], e1[8][2], e2[8][2], e3[8][2];
#pragma unroll
        for (int ks = 0; ks < 8; ++ks) {
            float2 p0 = __bfloat1622float2(*reinterpret_cast<__nv_bfloat162*>(&sf[ks][0]));
            float2 p1 = __bfloat1622float2(*reinterpret_cast<__nv_bfloat162*>(&sf[ks][1]));
            float2 p2 = __bfloat1622float2(*reinterpret_cast<__nv_bfloat162*>(&sf[ks][2]));
            float2 p3 = __bfloat1622float2(*reinterpret_cast<__nv_bfloat162*>(&sf[ks][3]));
            e0[ks][0] = p0.x; e0[ks][1] = p0.y;
            e1[ks][0] = p1.x; e1[ks][1] = p1.y;
            e2[ks][0] = p2.x; e2[ks][1] = p2.y;
            e3[ks][0] = p3.x; e3[ks][1] = p3.y;
        }

        // ---- online softmax (row g -> [0], row g+8 -> [1]) ----
        float rmax[2] = {-CUDART_INF_F, -CUDART_INF_F};
#pragma unroll
        for (int ks = 0; ks < 8; ++ks) {
            rmax[0] = fmaxf(rmax[0], fmaxf(fmaxf(e0[ks][0], e0[ks][1]),
                                           fmaxf(e2[ks][0], e2[ks][1])));
            rmax[1] = fmaxf(rmax[1], fmaxf(fmaxf(e1[ks][0], e1[ks][1]),
                                           fmaxf(e3[ks][0], e3[ks][1])));
        }
#pragma unroll
        for (int h = 0; h < 2; ++h) {
            rmax[h] = fmaxf(rmax[h], __shfl_xor_sync(0xffffffffu, rmax[h], 1));
            rmax[h] = fmaxf(rmax[h], __shfl_xor_sync(0xffffffffu, rmax[h], 2));
        }
        float scl[2], rsum[2] = {0.0f, 0.0f};
#pragma unroll
        for (int h = 0; h < 2; ++h) {
            const float mnew = fmaxf(mst[h], rmax[h]);
            scl[h] = __expf(mst[h] - mnew);
            mst[h] = mnew;
        }
        uint32_t af[8][4];
#pragma unroll
        for (int ks = 0; ks < 8; ++ks) {
            e0[ks][0] = __expf(e0[ks][0] - mst[0]); e0[ks][1] = __expf(e0[ks][1] - mst[0]);
            e2[ks][0] = __expf(e2[ks][0] - mst[0]); e2[ks][1] = __expf(e2[ks][1] - mst[0]);
            e1[ks][0] = __expf(e1[ks][0] - mst[1]); e1[ks][1] = __expf(e1[ks][1] - mst[1]);
            e3[ks][0] = __expf(e3[ks][0] - mst[1]); e3[ks][1] = __expf(e3[ks][1] - mst[1]);
            rsum[0] += e0[ks][0] + e0[ks][1] + e2[ks][0] + e2[ks][1];
            rsum[1] += e1[ks][0] + e1[ks][1] + e3[ks][0] + e3[ks][1];
            __nv_bfloat162 q0 = __floats2bfloat162_rn(e0[ks][0], e0[ks][1]);
            __nv_bfloat162 q1 = __floats2bfloat162_rn(e1[ks][0], e1[ks][1]);
            __nv_bfloat162 q2 = __floats2bfloat162_rn(e2[ks][0], e2[ks][1]);
            __nv_bfloat162 q3 = __floats2bfloat162_rn(e3[ks][0], e3[ks][1]);
            af[ks][0] = *reinterpret_cast<uint32_t*>(&q0);
            af[ks][1] = *reinterpret_cast<uint32_t*>(&q1);
            af[ks][2] = *reinterpret_cast<uint32_t*>(&q2);
            af[ks][3] = *reinterpret_cast<uint32_t*>(&q3);
        }
#pragma unroll
        for (int h = 0; h < 2; ++h) {
            rsum[h] += __shfl_xor_sync(0xffffffffu, rsum[h], 1);
            rsum[h] += __shfl_xor_sync(0xffffffffu, rsum[h], 2);
            lst[h] = lst[h] * scl[h] + rsum[h];
        }
#pragma unroll
        for (int nt = 0; nt < 8; ++nt) {
            accO[nt][0] *= scl[0]; accO[nt][1] *= scl[0];
            accO[nt][2] *= scl[1]; accO[nt][3] *= scl[1];
        }

        // ---- O += P V ----
#pragma unroll
        for (int ks = 0; ks < 8; ++ks) {
            uint32_t bf[8][2];
            const int kb = ks * 32 + bko;
#pragma unroll
            for (int np = 0; np < 4; ++np) {
                const int row = np * 16 + bro;
                const int pr  = 2 * row + (kb >> 7);
                ldsm4(bf[2 * np][0], bf[2 * np][1], bf[2 * np + 1][0], bf[2 * np + 1][1],
                      sV + pr * 128 + ((kb & 127) ^ ((pr & 7) << 4)));
            }
#pragma unroll
            for (int nt = 0; nt < 8; ++nt)
                mma_bf16(accO[nt], af[ks], bf[nt]);
        }
    }

    // ---- epilogue: O / l -> ctx[B,S,H] bf16 ----
#pragma unroll
    for (int h = 0; h < 2; ++h) {
        const int sI = m0 + wid * 16 + g + 8 * h;
        __nv_bfloat16* crow = ctx + ((size_t)bb * Sq + sI) * Hq + hh * HDq;
        const float inv = 1.0f / lst[h];
#pragma unroll
        for (int nt = 0; nt < 8; ++nt) {
            const int d = nt * 8 + 2 * tig;
            *reinterpret_cast<__nv_bfloat162*>(crow + d) =
                __floats2bfloat162_rn(accO[nt][2 * h + 0] * inv,
                                      accO[nt][2 * h + 1] * inv);
        }
    }
}

// ---------------------------------------------------------------------------
// Launch
// ---------------------------------------------------------------------------
extern "C" void kernel_launch(void* const* d_in, const int* in_sizes, int n_in,
                              void* d_out, int out_size) {
    const float* hs   = (const float*)d_in[0];
    const float* mask = (const float*)d_in[1];
    const float* wq   = (const float*)d_in[2];
    const float* bq   = (const float*)d_in[3];
    const float* wk   = (const float*)d_in[4];
    const float* bk   = (const float*)d_in[5];
    const float* wv   = (const float*)d_in[6];
    const float* bv   = (const float*)d_in[7];
    const float* wo   = (const float*)d_in[8];
    const float* bo   = (const float*)d_in[9];
    const float* gam  = (const float*)d_in[10];
    const float* bet  = (const float*)d_in[11];
    float* out = (float*)d_out;

    __nv_bfloat16 *xln, *bwq, *bwk, *bwv, *bwo, *q, *k, *v, *sc, *ctx;
    cudaGetSymbolAddress((void**)&xln, g_xln);
    cudaGetSymbolAddress((void**)&bwq, g_wq);
    cudaGetSymbolAddress((void**)&bwk, g_wk);
    cudaGetSymbolAddress((void**)&bwv, g_wv);
    cudaGetSymbolAddress((void**)&bwo, g_wo);
    cudaGetSymbolAddress((void**)&q,   g_q);
    cudaGetSymbolAddress((void**)&k,   g_k);
    cudaGetSymbolAddress((void**)&v,   g_v);
    cudaGetSymbolAddress((void**)&sc,  g_sc);
    cudaGetSymbolAddress((void**)&ctx, g_ctx);

    constexpr int SMW = 3 * (128 * 128 + 64 * 128);  // 73728
    cudaFuncSetAttribute((const void*)wmma_k<0>, cudaFuncAttributeMaxDynamicSharedMemorySize, SMW);
    cudaFuncSetAttribute((const void*)wmma_k<1>, cudaFuncAttributeMaxDynamicSharedMemorySize, SMW);
    cudaFuncSetAttribute((const void*)wmma_k<2>, cudaFuncAttributeMaxDynamicSharedMemorySize, SMW);
    cudaFuncSetAttribute((const void*)wmma_k<4>, cudaFuncAttributeMaxDynamicSharedMemorySize, SMW);
    cudaFuncSetAttribute((const void*)spv_k, cudaFuncAttributeMaxDynamicSharedMemorySize, SPV_SMEM);

    // 0) weight conversions (independent of LN)
    constexpr int N4 = Hq * Hq / 4;
    cvt_k<<<(N4 + 255) / 256, 256>>>((const float4*)wq, (__nv_bfloat162*)bwq, N4);
    cvt_k<<<(N4 + 255) / 256, 256>>>((const float4*)wk, (__nv_bfloat162*)bwk, N4);
    cvt_k<<<(N4 + 255) / 256, 256>>>((const float4*)wv, (__nv_bfloat162*)bwv, N4);
    cvt_k<<<(N4 + 255) / 256, 256>>>((const float4*)wo, (__nv_bfloat162*)bwo, N4);

    // 1) LayerNorm -> bf16
    ln_k<<<Mq, 256>>>(hs, gam, bet, xln);

    // 2) QKV projections. Q pre-scaled by 1/8; V written transposed.
    wmma_k<1><<<dim3(Hq / 64, Mq / 128, 1), 256, SMW>>>(
        xln, bwq, bq, nullptr, q, Hq, 0, 0, 0, 0.125f);
    wmma_k<1><<<dim3(Hq / 64, Mq / 128, 1), 256, SMW>>>(
        xln, bwk, bk, nullptr, k, Hq, 0, 0, 0, 1.0f);
    wmma_k<4><<<dim3(Hq / 64, Mq / 128, 1), 256, SMW>>>(
        xln, bwv, bv, nullptr, v, Hq, 0, 0, 0, 1.0f);

    // 3) scores = Q K^T + mask (bf16 out), batched over B*NH=32, K=64
    wmma_k<2><<<dim3(Sq / 64, Sq / 128, Bq * NHq), 256, SMW>>>(
        q, k, nullptr, mask, sc, HDq,
        (long)Sq * HDq, (long)Sq * HDq, (long)Sq * Sq, 1.0f);

    // 4) fused online-softmax + PV -> ctx (bf16)
    spv_k<<<dim3(Sq / 128, Bq * NHq), 256, SPV_SMEM>>>(sc, v, ctx);

    // 5) out = ctx Wo^T + bo + residual (fp32 out)
    wmma_k<0><<<dim3(Hq / 64, Mq / 128, 1), 256, SMW>>>(
        ctx, bwo, bo, hs, out, Hq, 0, 0, 0, 1.0f);
}

// round 8
// speedup vs baseline: 3.1237x; 1.4812x over previous
#include <cuda_runtime.h>
#include <cuda_bf16.h>
#include <cstdint>
#include <math_constants.h>

// Problem constants
#define Bq 2
#define Sq 2048
#define Hq 1024
#define NHq 16
#define HDq 64
#define Mq (Bq * Sq)   // 4096

// ---------------------------------------------------------------------------
// Scratch (device globals — no allocation allowed). All intermediates bf16.
// ---------------------------------------------------------------------------
__device__ __nv_bfloat16 g_xln[(size_t)Mq * Hq];                 // 8 MB
__device__ __nv_bfloat16 g_wq[(size_t)Hq * Hq];                  // 2 MB
__device__ __nv_bfloat16 g_wk[(size_t)Hq * Hq];
__device__ __nv_bfloat16 g_wv[(size_t)Hq * Hq];
__device__ __nv_bfloat16 g_wo[(size_t)Hq * Hq];
__device__ __nv_bfloat16 g_q[(size_t)Mq * Hq];                   // 8 MB [B,NH,S,HD] (pre-scaled)
__device__ __nv_bfloat16 g_k[(size_t)Mq * Hq];                   // 8 MB [B,NH,S,HD]
__device__ __nv_bfloat16 g_v[(size_t)Mq * Hq];                   // 8 MB [B,NH,HD,S] (transposed)
__device__ __nv_bfloat16 g_ctx[(size_t)Mq * Hq];                 // 8 MB [B,S,H]

// ---------------------------------------------------------------------------
// PTX helpers (sm_80-level — tcgen05 unavailable on compute_103 target)
// ---------------------------------------------------------------------------
__device__ __forceinline__ uint32_t smem_to_u32(const void* p) {
    uint32_t a;
    asm("{ .reg .u64 t; cvta.to.shared.u64 t, %1; cvt.u32.u64 %0, t; }" : "=r"(a) : "l"(p));
    return a;
}
__device__ __forceinline__ void cp_async16(uint32_t dst, const void* src) {
    asm volatile("cp.async.cg.shared.global [%0], [%1], 16;" :: "r"(dst), "l"(src));
}
__device__ __forceinline__ void cp_commit() {
    asm volatile("cp.async.commit_group;" ::: "memory");
}
__device__ __forceinline__ void ldsm4(uint32_t& r0, uint32_t& r1, uint32_t& r2,
                                      uint32_t& r3, uint32_t addr) {
    asm volatile("ldmatrix.sync.aligned.m8n8.x4.shared.b16 {%0,%1,%2,%3}, [%4];"
                 : "=r"(r0), "=r"(r1), "=r"(r2), "=r"(r3) : "r"(addr));
}
// m16n8k16 bf16 MMA, fp32 accumulate
__device__ __forceinline__ void mma_bf16(float* c, const uint32_t* a, const uint32_t* b) {
    asm volatile("mma.sync.aligned.m16n8k16.row.col.f32.bf16.bf16.f32 "
                 "{%0,%1,%2,%3}, {%4,%5,%6,%7}, {%8,%9}, {%0,%1,%2,%3};"
                 : "+f"(c[0]), "+f"(c[1]), "+f"(c[2]), "+f"(c[3])
                 : "r"(a[0]), "r"(a[1]), "r"(a[2]), "r"(a[3]), "r"(b[0]), "r"(b[1]));
}
__device__ __forceinline__ uint32_t packbf(float a, float b) {
    __nv_bfloat162 t = __floats2bfloat162_rn(a, b);
    return *reinterpret_cast<uint32_t*>(&t);
}

// ---------------------------------------------------------------------------
// LayerNorm: fp32 in -> bf16 out
// ---------------------------------------------------------------------------
__global__ __launch_bounds__(256) void ln_k(const float* __restrict__ x,
                                            const float* __restrict__ gamma,
                                            const float* __restrict__ beta,
                                            __nv_bfloat16* __restrict__ out) {
    const int row = blockIdx.x;
    const int tid = threadIdx.x;
    const float* xr = x + (size_t)row * Hq;

    float4 v = reinterpret_cast<const float4*>(xr)[tid];
    float s  = v.x + v.y + v.z + v.w;
    float ss = v.x * v.x + v.y * v.y + v.z * v.z + v.w * v.w;

    __shared__ float red[256];
    red[tid] = s; __syncthreads();
    for (int off = 128; off > 0; off >>= 1) {
        if (tid < off) red[tid] += red[tid + off];
        __syncthreads();
    }
    const float mean = red[0] * (1.0f / Hq);
    __syncthreads();
    red[tid] = ss; __syncthreads();
    for (int off = 128; off > 0; off >>= 1) {
        if (tid < off) red[tid] += red[tid + off];
        __syncthreads();
    }
    const float var  = red[0] * (1.0f / Hq) - mean * mean;
    const float rstd = rsqrtf(var + 1e-12f);

    float4 g = reinterpret_cast<const float4*>(gamma)[tid];
    float4 b = reinterpret_cast<const float4*>(beta)[tid];
    __nv_bfloat162* orow = reinterpret_cast<__nv_bfloat162*>(out + (size_t)row * Hq);
    orow[2 * tid]     = __floats2bfloat162_rn((v.x - mean) * rstd * g.x + b.x,
                                              (v.y - mean) * rstd * g.y + b.y);
    orow[2 * tid + 1] = __floats2bfloat162_rn((v.z - mean) * rstd * g.z + b.z,
                                              (v.w - mean) * rstd * g.w + b.w);
}

// ---------------------------------------------------------------------------
// fp32 -> bf16 conversion for all 4 weight matrices in one launch
// ---------------------------------------------------------------------------
__global__ __launch_bounds__(256) void cvt4_k(const float4* __restrict__ s0,
                                              const float4* __restrict__ s1,
                                              const float4* __restrict__ s2,
                                              const float4* __restrict__ s3,
                                              __nv_bfloat162* __restrict__ d0,
                                              __nv_bfloat162* __restrict__ d1,
                                              __nv_bfloat162* __restrict__ d2,
                                              __nv_bfloat162* __restrict__ d3, int n4) {
    const int i = blockIdx.x * 256 + threadIdx.x;
    if (i >= n4) return;
    const float4* src = (blockIdx.y == 0) ? s0 : (blockIdx.y == 1) ? s1
                        : (blockIdx.y == 2) ? s2 : s3;
    __nv_bfloat162* dst = (blockIdx.y == 0) ? d0 : (blockIdx.y == 1) ? d1
                          : (blockIdx.y == 2) ? d2 : d3;
    float4 v = src[i];
    dst[2 * i]     = __floats2bfloat162_rn(v.x, v.y);
    dst[2 * i + 1] = __floats2bfloat162_rn(v.z, v.w);
}

// ---------------------------------------------------------------------------
// bf16 mma.sync NT GEMM:  C_tile[128, 64] = A[M,K] * B[N,K]^T (both K-major)
// MODE 0: out-proj (+bias+residual) -> fp32; MODE 1: Q/K proj -> bf16 head
// layout; MODE 4: V proj -> bf16 [B,NH,HD,S] transposed.
// ---------------------------------------------------------------------------
template <int MODE>
__global__ __launch_bounds__(256, 2)
void wmma_k(const __nv_bfloat16* __restrict__ A, const __nv_bfloat16* __restrict__ B,
            const float* __restrict__ bias, const float* __restrict__ extra,
            void* __restrict__ Cv, int Kdim, float scale) {
    constexpr int STAGES = 3;
    constexpr int ASZ = 128 * 128;
    constexpr int BSZ = 64 * 128;
    constexpr int STG = ASZ + BSZ;
    constexpr int MT = 2, NT = 4;

    extern __shared__ char smem[];
    const uint32_t sbase = smem_to_u32(smem);

    const int tid  = threadIdx.x;
    const int wid  = tid >> 5;
    const int lane = tid & 31;
    const int m0   = blockIdx.y * 128;
    const int n0   = blockIdx.x * 64;

    const int wm0 = (wid & 3) * 32;
    const int wn0 = (wid >> 2) * 32;

    const int KT = Kdim >> 6;

    auto issue = [&](int kt) {
        const uint32_t abase = sbase + (uint32_t)(kt % STAGES) * STG;
        const __nv_bfloat16* Ak = A + (size_t)kt * 64;
#pragma unroll
        for (int i = 0; i < 4; ++i) {
            const int idx = tid + i * 256, r = idx >> 3, c = idx & 7;
            cp_async16(abase + r * 128 + ((c * 16) ^ ((r & 7) << 4)),
                       Ak + (size_t)(m0 + r) * Kdim + c * 8);
        }
        const uint32_t bbase = abase + ASZ;
        const __nv_bfloat16* Bk = B + (size_t)kt * 64;
#pragma unroll
        for (int i = 0; i < 2; ++i) {
            const int idx = tid + i * 256, r = idx >> 3, c = idx & 7;
            cp_async16(bbase + r * 128 + ((c * 16) ^ ((r & 7) << 4)),
                       Bk + (size_t)(n0 + r) * Kdim + c * 8);
        }
    };

    float acc[MT][NT][4];
#pragma unroll
    for (int i = 0; i < MT; ++i)
#pragma unroll
        for (int j = 0; j < NT; ++j)
#pragma unroll
            for (int e = 0; e < 4; ++e) acc[i][j][e] = 0.0f;

    const int mat = lane >> 3, mr = lane & 7;
    const int aro = (mat & 1) * 8 + mr;
    const int ako = (mat >> 1) * 16;
    const int bro = (mat >> 1) * 8 + mr;
    const int bko = (mat & 1) * 16;

    for (int kt = 0; kt < STAGES - 1; ++kt) {
        if (kt < KT) issue(kt);
        cp_commit();
    }

    for (int kt = 0; kt < KT; ++kt) {
        asm volatile("cp.async.wait_group %0;" :: "n"(STAGES - 2) : "memory");
        __syncthreads();
        if (kt + STAGES - 1 < KT) issue(kt + STAGES - 1);
        cp_commit();

        const uint32_t abase = sbase + (uint32_t)(kt % STAGES) * STG;
        const uint32_t bbase = abase + ASZ;
#pragma unroll
        for (int ks = 0; ks < 4; ++ks) {
            uint32_t af[MT][4], bf[NT][2];
#pragma unroll
            for (int mt = 0; mt < MT; ++mt) {
                const int row = wm0 + mt * 16 + aro;
                const int kb  = ks * 32 + ako;
                ldsm4(af[mt][0], af[mt][1], af[mt][2], af[mt][3],
                      abase + row * 128 + (kb ^ ((row & 7) << 4)));
            }
#pragma unroll
            for (int np = 0; np < NT / 2; ++np) {
                const int row = wn0 + np * 16 + bro;
                const int kb  = ks * 32 + bko;
                ldsm4(bf[2 * np][0], bf[2 * np][1], bf[2 * np + 1][0], bf[2 * np + 1][1],
                      bbase + row * 128 + (kb ^ ((row & 7) << 4)));
            }
#pragma unroll
            for (int mt = 0; mt < MT; ++mt)
#pragma unroll
                for (int nt = 0; nt < NT; ++nt)
                    mma_bf16(acc[mt][nt], af[mt], bf[nt]);
        }
    }

    const int g = lane >> 2, tig = lane & 3;
#pragma unroll
    for (int mt = 0; mt < MT; ++mt) {
#pragma unroll
        for (int half = 0; half < 2; ++half) {
            const int m = m0 + wm0 + mt * 16 + g + half * 8;
#pragma unroll
            for (int nt = 0; nt < NT; ++nt) {
                const int n = n0 + wn0 + nt * 8 + 2 * tig;
                const float c0 = acc[mt][nt][half * 2 + 0];
                const float c1 = acc[mt][nt][half * 2 + 1];
                if (MODE == 0) {
                    float* C = (float*)Cv;
                    const float2 bi = *reinterpret_cast<const float2*>(bias + n);
                    const float2 ex = *reinterpret_cast<const float2*>(extra + (size_t)m * Hq + n);
                    float2 o; o.x = c0 + bi.x + ex.x; o.y = c1 + bi.y + ex.y;
                    *reinterpret_cast<float2*>(C + (size_t)m * Hq + n) = o;
                } else if (MODE == 1) {
                    __nv_bfloat16* C = (__nv_bfloat16*)Cv;
                    const float2 bi = *reinterpret_cast<const float2*>(bias + n);
                    const int bb = m >> 11, sI = m & (Sq - 1);
                    const int h = n >> 6, d = n & 63;
                    *reinterpret_cast<__nv_bfloat162*>(
                        C + (((size_t)bb * NHq + h) * Sq + sI) * HDq + d) =
                        __floats2bfloat162_rn((c0 + bi.x) * scale, (c1 + bi.y) * scale);
                } else {  // MODE 4: V transposed [B,NH,HD,S]
                    __nv_bfloat16* C = (__nv_bfloat16*)Cv;
                    const int bb = m >> 11, sI = m & (Sq - 1);
                    const int h = n >> 6, d = n & 63;
                    __nv_bfloat16* dst = C + (((size_t)bb * NHq + h) * HDq + d) * Sq + sI;
                    dst[0]  = __float2bfloat16(c0 + bias[n]);
                    dst[Sq] = __float2bfloat16(c1 + bias[n + 1]);
                }
            }
        }
    }
}

// ---------------------------------------------------------------------------
// Flash attention (bf16): ctx = softmax(Q K^T + mask) V, fully in-register P.
//   Q,K: [B,NH,S,HD] bf16 (Q pre-scaled); V: [B,NH,HD,S] bf16 transposed.
// Grid (Sq/128, B*NH), 256 thr, 8 warps x 16 Q rows, 32 iters of 64 KV cols.
// bf16 trick: m16n8 C-fragments of S pack pairwise into m16n8k16 A-fragments,
// so exp(S) feeds the PV MMA with no smem round-trip.
// smem: Q 16K | K 2x8K | V 2x8K | mask 8K = 56 KB
// ---------------------------------------------------------------------------
#define FL_Q 0
#define FL_K 16384
#define FL_V 32768
#define FL_M 49152
#define FL_SMEM 57344
#define BKV 64
#define NIT (Sq / BKV)   // 32

__global__ __launch_bounds__(256, 2)
void flash_k(const __nv_bfloat16* __restrict__ Qg, const __nv_bfloat16* __restrict__ Kg,
             const __nv_bfloat16* __restrict__ Vt, const float* __restrict__ mask,
             __nv_bfloat16* __restrict__ ctx) {
    extern __shared__ char smem[];
    const uint32_t sb = smem_to_u32(smem);

    const int tid  = threadIdx.x;
    const int wid  = tid >> 5;
    const int lane = tid & 31;
    const int m0   = blockIdx.x * 128;
    const int bz   = blockIdx.y;
    const int bb   = bz >> 4, hh = bz & 15;

    const __nv_bfloat16* Qb = Qg + ((size_t)bz * Sq + m0) * HDq;
    const __nv_bfloat16* Kb = Kg + (size_t)bz * Sq * HDq;
    const __nv_bfloat16* Vb = Vt + (size_t)bz * HDq * Sq;
    const float* mrow = mask + (size_t)bb * Sq;

    // ---- load Q (128 rows x 128B) + mask row (8KB) once ----
#pragma unroll
    for (int i = 0; i < 4; ++i) {
        const int idx = tid + i * 256, r = idx >> 3, c = idx & 7;
        cp_async16(sb + FL_Q + r * 128 + ((c * 16) ^ ((r & 7) << 4)),
                   Qb + (size_t)r * HDq + c * 8);
    }
#pragma unroll
    for (int i = 0; i < 2; ++i) {
        const int idx = tid + i * 256;
        cp_async16(sb + FL_M + idx * 16, mrow + idx * 4);
    }

    auto issue_kv = [&](int it) {
        const uint32_t sK = sb + FL_K + (uint32_t)(it & 1) * 8192;
        const __nv_bfloat16* Ks = Kb + (size_t)it * BKV * HDq;
#pragma unroll
        for (int i = 0; i < 2; ++i) {
            const int idx = tid + i * 256, r = idx >> 3, c = idx & 7;
            cp_async16(sK + r * 128 + ((c * 16) ^ ((r & 7) << 4)),
                       Ks + (size_t)r * HDq + c * 8);
        }
        const uint32_t sV = sb + FL_V + (uint32_t)(it & 1) * 8192;
        const __nv_bfloat16* Vs = Vb + (size_t)it * BKV;
#pragma unroll
        for (int i = 0; i < 2; ++i) {
            const int idx = tid + i * 256, d = idx >> 3, c = idx & 7;
            cp_async16(sV + d * 128 + ((c * 16) ^ ((d & 7) << 4)),
                       Vs + (size_t)d * Sq + c * 8);
        }
    };

    issue_kv(0);
    cp_commit();

    const int mat = lane >> 3, mr = lane & 7;
    const int aro = (mat & 1) * 8 + mr;
    const int ako = (mat >> 1) * 16;
    const int bro = (mat >> 1) * 8 + mr;
    const int bko = (mat & 1) * 16;
    const int g   = lane >> 2, tig = lane & 3;

    asm volatile("cp.async.wait_group 0;" ::: "memory");
    __syncthreads();

    // ---- hoist Q fragments: HD=64 -> 4 k16 steps ----
    uint32_t qf[4][4];
#pragma unroll
    for (int ks = 0; ks < 4; ++ks) {
        const int row = wid * 16 + aro;
        const int kb  = ks * 32 + ako;
        ldsm4(qf[ks][0], qf[ks][1], qf[ks][2], qf[ks][3],
              sb + FL_Q + row * 128 + (kb ^ ((row & 7) << 4)));
    }

    float accO[8][4];
#pragma unroll
    for (int nt = 0; nt < 8; ++nt)
#pragma unroll
        for (int e = 0; e < 4; ++e) accO[nt][e] = 0.0f;
    float mst[2] = {-CUDART_INF_F, -CUDART_INF_F};
    float lst[2] = {0.0f, 0.0f};

    for (int it = 0; it < NIT; ++it) {
        if (it) {
            asm volatile("cp.async.wait_group 0;" ::: "memory");
            __syncthreads();
        }
        if (it + 1 < NIT) {
            issue_kv(it + 1);
            cp_commit();
        }

        const uint32_t sK = sb + FL_K + (uint32_t)(it & 1) * 8192;
        const uint32_t sV = sb + FL_V + (uint32_t)(it & 1) * 8192;

        // ---- S = Q K^T : warp tile 16 x 64 (C-fragments) ----
        float accS[8][4];
#pragma unroll
        for (int nt = 0; nt < 8; ++nt)
#pragma unroll
            for (int e = 0; e < 4; ++e) accS[nt][e] = 0.0f;
#pragma unroll
        for (int ks = 0; ks < 4; ++ks) {
            uint32_t bf[8][2];
            const int kb = ks * 32 + bko;
#pragma unroll
            for (int np = 0; np < 4; ++np) {
                const int row = np * 16 + bro;
                ldsm4(bf[2 * np][0], bf[2 * np][1], bf[2 * np + 1][0], bf[2 * np + 1][1],
                      sK + row * 128 + (kb ^ ((row & 7) << 4)));
            }
#pragma unroll
            for (int nt = 0; nt < 8; ++nt)
                mma_bf16(accS[nt], qf[ks], bf[nt]);
        }

        // ---- add mask (c0,c1: row g; c2,c3: row g+8 — same cols) ----
#pragma unroll
        for (int nt = 0; nt < 8; ++nt) {
            const float2 mk = *reinterpret_cast<const float2*>(
                smem + FL_M + (it * BKV + nt * 8 + 2 * tig) * 4);
            accS[nt][0] += mk.x; accS[nt][1] += mk.y;
            accS[nt][2] += mk.x; accS[nt][3] += mk.y;
        }

        // ---- online softmax: row g -> [0], row g+8 -> [1] ----
        float rmax[2] = {-CUDART_INF_F, -CUDART_INF_F};
#pragma unroll
        for (int nt = 0; nt < 8; ++nt) {
            rmax[0] = fmaxf(rmax[0], fmaxf(accS[nt][0], accS[nt][1]));
            rmax[1] = fmaxf(rmax[1], fmaxf(accS[nt][2], accS[nt][3]));
        }
#pragma unroll
        for (int h = 0; h < 2; ++h) {
            rmax[h] = fmaxf(rmax[h], __shfl_xor_sync(0xffffffffu, rmax[h], 1));
            rmax[h] = fmaxf(rmax[h], __shfl_xor_sync(0xffffffffu, rmax[h], 2));
        }
        float scl[2], rsum[2] = {0.0f, 0.0f};
#pragma unroll
        for (int h = 0; h < 2; ++h) {
            const float mnew = fmaxf(mst[h], rmax[h]);
            scl[h] = __expf(mst[h] - mnew);
            mst[h] = mnew;
        }
#pragma unroll
        for (int nt = 0; nt < 8; ++nt) {
            accS[nt][0] = __expf(accS[nt][0] - mst[0]);
            accS[nt][1] = __expf(accS[nt][1] - mst[0]);
            accS[nt][2] = __expf(accS[nt][2] - mst[1]);
            accS[nt][3] = __expf(accS[nt][3] - mst[1]);
            rsum[0] += accS[nt][0] + accS[nt][1];
            rsum[1] += accS[nt][2] + accS[nt][3];
        }
#pragma unroll
        for (int h = 0; h < 2; ++h) {
            rsum[h] += __shfl_xor_sync(0xffffffffu, rsum[h], 1);
            rsum[h] += __shfl_xor_sync(0xffffffffu, rsum[h], 2);
            lst[h] = lst[h] * scl[h] + rsum[h];
        }
#pragma unroll
        for (int nt = 0; nt < 8; ++nt) {
            accO[nt][0] *= scl[0]; accO[nt][1] *= scl[0];
            accO[nt][2] *= scl[1]; accO[nt][3] *= scl[1];
        }

        // ---- repack: C-fragments (2 n-tiles) -> one k16 A-fragment ----
        uint32_t af[4][4];
#pragma unroll
        for (int k2 = 0; k2 < 4; ++k2) {
            af[k2][0] = packbf(accS[2 * k2][0],     accS[2 * k2][1]);
            af[k2][1] = packbf(accS[2 * k2][2],     accS[2 * k2][3]);
            af[k2][2] = packbf(accS[2 * k2 + 1][0], accS[2 * k2 + 1][1]);
            af[k2][3] = packbf(accS[2 * k2 + 1][2], accS[2 * k2 + 1][3]);
        }

        // ---- O += P V (B from transposed V tile: 64 d-rows x 64 k-cols) ----
#pragma unroll
        for (int ks = 0; ks < 4; ++ks) {
            uint32_t bf[8][2];
            const int kb = ks * 32 + bko;
#pragma unroll
            for (int np = 0; np < 4; ++np) {
                const int row = np * 16 + bro;
                ldsm4(bf[2 * np][0], bf[2 * np][1], bf[2 * np + 1][0], bf[2 * np + 1][1],
                      sV + row * 128 + (kb ^ ((row & 7) << 4)));
            }
#pragma unroll
            for (int nt = 0; nt < 8; ++nt)
                mma_bf16(accO[nt], af[ks], bf[nt]);
        }
    }

    // ---- epilogue: O / l -> ctx[B,S,H] bf16 ----
#pragma unroll
    for (int h = 0; h < 2; ++h) {
        const int sI = m0 + wid * 16 + g + 8 * h;
        __nv_bfloat16* crow = ctx + ((size_t)bb * Sq + sI) * Hq + hh * HDq;
        const float inv = 1.0f / lst[h];
#pragma unroll
        for (int nt = 0; nt < 8; ++nt) {
            const int d = nt * 8 + 2 * tig;
            *reinterpret_cast<__nv_bfloat162*>(crow + d) =
                __floats2bfloat162_rn(accO[nt][2 * h + 0] * inv,
                                      accO[nt][2 * h + 1] * inv);
        }
    }
}

// ---------------------------------------------------------------------------
// Launch
// ---------------------------------------------------------------------------
extern "C" void kernel_launch(void* const* d_in, const int* in_sizes, int n_in,
                              void* d_out, int out_size) {
    const float* hs   = (const float*)d_in[0];
    const float* mask = (const float*)d_in[1];
    const float* wq   = (const float*)d_in[2];
    const float* bq   = (const float*)d_in[3];
    const float* wk   = (const float*)d_in[4];
    const float* bk   = (const float*)d_in[5];
    const float* wv   = (const float*)d_in[6];
    const float* bv   = (const float*)d_in[7];
    const float* wo   = (const float*)d_in[8];
    const float* bo   = (const float*)d_in[9];
    const float* gam  = (const float*)d_in[10];
    const float* bet  = (const float*)d_in[11];
    float* out = (float*)d_out;

    __nv_bfloat16 *xln, *bwq, *bwk, *bwv, *bwo, *q, *k, *v, *ctx;
    cudaGetSymbolAddress((void**)&xln, g_xln);
    cudaGetSymbolAddress((void**)&bwq, g_wq);
    cudaGetSymbolAddress((void**)&bwk, g_wk);
    cudaGetSymbolAddress((void**)&bwv, g_wv);
    cudaGetSymbolAddress((void**)&bwo, g_wo);
    cudaGetSymbolAddress((void**)&q,   g_q);
    cudaGetSymbolAddress((void**)&k,   g_k);
    cudaGetSymbolAddress((void**)&v,   g_v);
    cudaGetSymbolAddress((void**)&ctx, g_ctx);

    constexpr int SMW = 3 * (128 * 128 + 64 * 128);  // 73728
    cudaFuncSetAttribute((const void*)wmma_k<0>, cudaFuncAttributeMaxDynamicSharedMemorySize, SMW);
    cudaFuncSetAttribute((const void*)wmma_k<1>, cudaFuncAttributeMaxDynamicSharedMemorySize, SMW);
    cudaFuncSetAttribute((const void*)wmma_k<4>, cudaFuncAttributeMaxDynamicSharedMemorySize, SMW);
    cudaFuncSetAttribute((const void*)flash_k, cudaFuncAttributeMaxDynamicSharedMemorySize, FL_SMEM);

    // 0) all weight conversions, one launch
    constexpr int N4 = Hq * Hq / 4;
    cvt4_k<<<dim3((N4 + 255) / 256, 4), 256>>>(
        (const float4*)wq, (const float4*)wk, (const float4*)wv, (const float4*)wo,
        (__nv_bfloat162*)bwq, (__nv_bfloat162*)bwk, (__nv_bfloat162*)bwv,
        (__nv_bfloat162*)bwo, N4);

    // 1) LayerNorm -> bf16
    ln_k<<<Mq, 256>>>(hs, gam, bet, xln);

    // 2) QKV projections. Q pre-scaled by 1/8; V written transposed.
    wmma_k<1><<<dim3(Hq / 64, Mq / 128, 1), 256, SMW>>>(xln, bwq, bq, nullptr, q, Hq, 0.125f);
    wmma_k<1><<<dim3(Hq / 64, Mq / 128, 1), 256, SMW>>>(xln, bwk, bk, nullptr, k, Hq, 1.0f);
    wmma_k<4><<<dim3(Hq / 64, Mq / 128, 1), 256, SMW>>>(xln, bwv, bv, nullptr, v, Hq, 1.0f);

    // 3) flash attention -> ctx (bf16)
    flash_k<<<dim3(Sq / 128, Bq * NHq), 256, FL_SMEM>>>(q, k, v, mask, ctx);

    // 4) out = ctx Wo^T + bo + residual (fp32 out)
    wmma_k<0><<<dim3(Hq / 64, Mq / 128, 1), 256, SMW>>>(ctx, bwo, bo, hs, out, Hq, 1.0f);
}

// round 9
// speedup vs baseline: 3.4254x; 1.0966x over previous
#include <cuda_runtime.h>
#include <cuda_bf16.h>
#include <cstdint>
#include <math_constants.h>

// Problem constants
#define Bq 2
#define Sq 2048
#define Hq 1024
#define NHq 16
#define HDq 64
#define Mq (Bq * Sq)   // 4096

// ---------------------------------------------------------------------------
// Scratch (device globals — no allocation allowed). All intermediates bf16.
// ---------------------------------------------------------------------------
__device__ __nv_bfloat16 g_xln[(size_t)Mq * Hq];                 // 8 MB
__device__ __nv_bfloat16 g_wqkv[(size_t)3 * Hq * Hq];            // 6 MB packed [3072,1024]
__device__ __nv_bfloat16 g_wo[(size_t)Hq * Hq];                  // 2 MB
__device__ __nv_bfloat16 g_q[(size_t)Mq * Hq];                   // 8 MB [B,NH,S,HD] (pre-scaled)
__device__ __nv_bfloat16 g_k[(size_t)Mq * Hq];                   // 8 MB [B,NH,S,HD]
__device__ __nv_bfloat16 g_v[(size_t)Mq * Hq];                   // 8 MB [B,NH,HD,S] (transposed)
__device__ __nv_bfloat16 g_ctx[(size_t)Mq * Hq];                 // 8 MB [B,S,H]

// ---------------------------------------------------------------------------
// PTX helpers (sm_80-level — tcgen05 unavailable on compute_103 target)
// ---------------------------------------------------------------------------
__device__ __forceinline__ uint32_t smem_to_u32(const void* p) {
    uint32_t a;
    asm("{ .reg .u64 t; cvta.to.shared.u64 t, %1; cvt.u32.u64 %0, t; }" : "=r"(a) : "l"(p));
    return a;
}
__device__ __forceinline__ void cp_async16(uint32_t dst, const void* src) {
    asm volatile("cp.async.cg.shared.global [%0], [%1], 16;" :: "r"(dst), "l"(src));
}
__device__ __forceinline__ void cp_commit() {
    asm volatile("cp.async.commit_group;" ::: "memory");
}
__device__ __forceinline__ void ldsm4(uint32_t& r0, uint32_t& r1, uint32_t& r2,
                                      uint32_t& r3, uint32_t addr) {
    asm volatile("ldmatrix.sync.aligned.m8n8.x4.shared.b16 {%0,%1,%2,%3}, [%4];"
                 : "=r"(r0), "=r"(r1), "=r"(r2), "=r"(r3) : "r"(addr));
}
// m16n8k16 bf16 MMA, fp32 accumulate
__device__ __forceinline__ void mma_bf16(float* c, const uint32_t* a, const uint32_t* b) {
    asm volatile("mma.sync.aligned.m16n8k16.row.col.f32.bf16.bf16.f32 "
                 "{%0,%1,%2,%3}, {%4,%5,%6,%7}, {%8,%9}, {%0,%1,%2,%3};"
                 : "+f"(c[0]), "+f"(c[1]), "+f"(c[2]), "+f"(c[3])
                 : "r"(a[0]), "r"(a[1]), "r"(a[2]), "r"(a[3]), "r"(b[0]), "r"(b[1]));
}
__device__ __forceinline__ uint32_t packbf(float a, float b) {
    __nv_bfloat162 t = __floats2bfloat162_rn(a, b);
    return *reinterpret_cast<uint32_t*>(&t);
}

// ---------------------------------------------------------------------------
// LayerNorm: fp32 in -> bf16 out
// ---------------------------------------------------------------------------
__global__ __launch_bounds__(256) void ln_k(const float* __restrict__ x,
                                            const float* __restrict__ gamma,
                                            const float* __restrict__ beta,
                                            __nv_bfloat16* __restrict__ out) {
    const int row = blockIdx.x;
    const int tid = threadIdx.x;
    const float* xr = x + (size_t)row * Hq;

    float4 v = reinterpret_cast<const float4*>(xr)[tid];
    float s  = v.x + v.y + v.z + v.w;
    float ss = v.x * v.x + v.y * v.y + v.z * v.z + v.w * v.w;

    __shared__ float red[256];
    red[tid] = s; __syncthreads();
    for (int off = 128; off > 0; off >>= 1) {
        if (tid < off) red[tid] += red[tid + off];
        __syncthreads();
    }
    const float mean = red[0] * (1.0f / Hq);
    __syncthreads();
    red[tid] = ss; __syncthreads();
    for (int off = 128; off > 0; off >>= 1) {
        if (tid < off) red[tid] += red[tid + off];
        __syncthreads();
    }
    const float var  = red[0] * (1.0f / Hq) - mean * mean;
    const float rstd = rsqrtf(var + 1e-12f);

    float4 g = reinterpret_cast<const float4*>(gamma)[tid];
    float4 b = reinterpret_cast<const float4*>(beta)[tid];
    __nv_bfloat162* orow = reinterpret_cast<__nv_bfloat162*>(out + (size_t)row * Hq);
    orow[2 * tid]     = __floats2bfloat162_rn((v.x - mean) * rstd * g.x + b.x,
                                              (v.y - mean) * rstd * g.y + b.y);
    orow[2 * tid + 1] = __floats2bfloat162_rn((v.z - mean) * rstd * g.z + b.z,
                                              (v.w - mean) * rstd * g.w + b.w);
}

// ---------------------------------------------------------------------------
// fp32 -> bf16 conversion for all 4 weight matrices (wq/wk/wv packed + wo)
// ---------------------------------------------------------------------------
__global__ __launch_bounds__(256) void cvt4_k(const float4* __restrict__ s0,
                                              const float4* __restrict__ s1,
                                              const float4* __restrict__ s2,
                                              const float4* __restrict__ s3,
                                              __nv_bfloat162* __restrict__ dqkv,
                                              __nv_bfloat162* __restrict__ dwo, int n4) {
    const int i = blockIdx.x * 256 + threadIdx.x;
    if (i >= n4) return;
    const float4* src = (blockIdx.y == 0) ? s0 : (blockIdx.y == 1) ? s1
                        : (blockIdx.y == 2) ? s2 : s3;
    __nv_bfloat162* dst = (blockIdx.y == 3) ? dwo : dqkv + (size_t)blockIdx.y * (Hq * Hq / 2);
    float4 v = src[i];
    dst[2 * i]     = __floats2bfloat162_rn(v.x, v.y);
    dst[2 * i + 1] = __floats2bfloat162_rn(v.z, v.w);
}

// ---------------------------------------------------------------------------
// bf16 mma.sync NT GEMM:  C_tile[128, 128] = A[M,K] * B[N,K]^T (both K-major)
// 8 warps as 4x2 grid of 32x64 warp tiles (MT=2, NT=8); 3-stage cp.async.
// MODE 0: out-proj (+bias+residual) -> fp32 [B*S, H]
// MODE 5: merged QKV: per-CTA route by n0>>10:
//         mat 0: Q (+bq, *1/8) -> bf16 head layout
//         mat 1: K (+bk)       -> bf16 head layout
//         mat 2: V (+bv)       -> bf16 [B,NH,HD,S] transposed
// ---------------------------------------------------------------------------
template <int MODE>
__global__ __launch_bounds__(256)
void wmma_k(const __nv_bfloat16* __restrict__ A, const __nv_bfloat16* __restrict__ B,
            const float* __restrict__ b0, const float* __restrict__ b1,
            const float* __restrict__ b2, const float* __restrict__ extra,
            void* __restrict__ C0, void* __restrict__ C1, void* __restrict__ C2,
            int Kdim) {
    constexpr int STAGES = 3;
    constexpr int ASZ = 128 * 128;   // 16 KB
    constexpr int BSZ = 128 * 128;   // 16 KB
    constexpr int STG = ASZ + BSZ;
    constexpr int MT = 2, NT = 8;

    extern __shared__ char smem[];
    const uint32_t sbase = smem_to_u32(smem);

    const int tid  = threadIdx.x;
    const int wid  = tid >> 5;
    const int lane = tid & 31;
    const int m0   = blockIdx.y * 128;
    const int n0   = blockIdx.x * 128;

    const int wm0 = (wid & 3) * 32;
    const int wn0 = (wid >> 2) * 64;

    const int KT = Kdim >> 6;

    auto issue = [&](int kt) {
        const uint32_t abase = sbase + (uint32_t)(kt % STAGES) * STG;
        const __nv_bfloat16* Ak = A + (size_t)kt * 64;
#pragma unroll
        for (int i = 0; i < 4; ++i) {
            const int idx = tid + i * 256, r = idx >> 3, c = idx & 7;
            cp_async16(abase + r * 128 + ((c * 16) ^ ((r & 7) << 4)),
                       Ak + (size_t)(m0 + r) * Kdim + c * 8);
        }
        const uint32_t bbase = abase + ASZ;
        const __nv_bfloat16* Bk = B + (size_t)kt * 64;
#pragma unroll
        for (int i = 0; i < 4; ++i) {
            const int idx = tid + i * 256, r = idx >> 3, c = idx & 7;
            cp_async16(bbase + r * 128 + ((c * 16) ^ ((r & 7) << 4)),
                       Bk + (size_t)(n0 + r) * Kdim + c * 8);
        }
    };

    float acc[MT][NT][4];
#pragma unroll
    for (int i = 0; i < MT; ++i)
#pragma unroll
        for (int j = 0; j < NT; ++j)
#pragma unroll
            for (int e = 0; e < 4; ++e) acc[i][j][e] = 0.0f;

    const int mat = lane >> 3, mr = lane & 7;
    const int aro = (mat & 1) * 8 + mr;
    const int ako = (mat >> 1) * 16;
    const int bro = (mat >> 1) * 8 + mr;
    const int bko = (mat & 1) * 16;

    for (int kt = 0; kt < STAGES - 1; ++kt) {
        if (kt < KT) issue(kt);
        cp_commit();
    }

    for (int kt = 0; kt < KT; ++kt) {
        asm volatile("cp.async.wait_group %0;" :: "n"(STAGES - 2) : "memory");
        __syncthreads();
        if (kt + STAGES - 1 < KT) issue(kt + STAGES - 1);
        cp_commit();

        const uint32_t abase = sbase + (uint32_t)(kt % STAGES) * STG;
        const uint32_t bbase = abase + ASZ;
#pragma unroll
        for (int ks = 0; ks < 4; ++ks) {
            uint32_t af[MT][4], bf[NT][2];
#pragma unroll
            for (int mt = 0; mt < MT; ++mt) {
                const int row = wm0 + mt * 16 + aro;
                const int kb  = ks * 32 + ako;
                ldsm4(af[mt][0], af[mt][1], af[mt][2], af[mt][3],
                      abase + row * 128 + (kb ^ ((row & 7) << 4)));
            }
#pragma unroll
            for (int np = 0; np < NT / 2; ++np) {
                const int row = wn0 + np * 16 + bro;
                const int kb  = ks * 32 + bko;
                ldsm4(bf[2 * np][0], bf[2 * np][1], bf[2 * np + 1][0], bf[2 * np + 1][1],
                      bbase + row * 128 + (kb ^ ((row & 7) << 4)));
            }
#pragma unroll
            for (int mt = 0; mt < MT; ++mt)
#pragma unroll
                for (int nt = 0; nt < NT; ++nt)
                    mma_bf16(acc[mt][nt], af[mt], bf[nt]);
        }
    }

    const int g = lane >> 2, tig = lane & 3;

    if (MODE == 0) {
        float* C = (float*)C0;
#pragma unroll
        for (int mt = 0; mt < MT; ++mt) {
#pragma unroll
            for (int half = 0; half < 2; ++half) {
                const int m = m0 + wm0 + mt * 16 + g + half * 8;
#pragma unroll
                for (int nt = 0; nt < NT; ++nt) {
                    const int n = n0 + wn0 + nt * 8 + 2 * tig;
                    const float2 bi = *reinterpret_cast<const float2*>(b0 + n);
                    const float2 ex = *reinterpret_cast<const float2*>(extra + (size_t)m * Hq + n);
                    float2 o;
                    o.x = acc[mt][nt][half * 2 + 0] + bi.x + ex.x;
                    o.y = acc[mt][nt][half * 2 + 1] + bi.y + ex.y;
                    *reinterpret_cast<float2*>(C + (size_t)m * Hq + n) = o;
                }
            }
        }
    } else {
        const int matid = n0 >> 10;             // 0=Q, 1=K, 2=V
        const float scale = (matid == 0) ? 0.125f : 1.0f;
        const float* bias = (matid == 0) ? b0 : (matid == 1) ? b1 : b2;
        __nv_bfloat16* C = (__nv_bfloat16*)((matid == 0) ? C0 : (matid == 1) ? C1 : C2);
#pragma unroll
        for (int mt = 0; mt < MT; ++mt) {
#pragma unroll
            for (int half = 0; half < 2; ++half) {
                const int m = m0 + wm0 + mt * 16 + g + half * 8;
                const int bb = m >> 11, sI = m & (Sq - 1);
#pragma unroll
                for (int nt = 0; nt < NT; ++nt) {
                    const int n  = (n0 & 1023) + wn0 + nt * 8 + 2 * tig;
                    const int h  = n >> 6, d = n & 63;
                    const float2 bi = *reinterpret_cast<const float2*>(bias + n);
                    const float c0 = (acc[mt][nt][half * 2 + 0] + bi.x) * scale;
                    const float c1 = (acc[mt][nt][half * 2 + 1] + bi.y) * scale;
                    if (matid < 2) {
                        *reinterpret_cast<__nv_bfloat162*>(
                            C + (((size_t)bb * NHq + h) * Sq + sI) * HDq + d) =
                            __floats2bfloat162_rn(c0, c1);
                    } else {
                        __nv_bfloat16* dst = C + (((size_t)bb * NHq + h) * HDq + d) * Sq + sI;
                        dst[0]  = __float2bfloat16(c0);
                        dst[Sq] = __float2bfloat16(c1);
                    }
                }
            }
        }
    }
}

// ---------------------------------------------------------------------------
// Flash attention (bf16): ctx = softmax(Q K^T + mask) V, fully in-register P.
// Grid (Sq/128, B*NH), 256 thr, 8 warps x 16 Q rows, 32 iters of 64 KV cols.
// smem: Q 16K | K 2x8K | V 2x8K | mask 8K = 56 KB
// ---------------------------------------------------------------------------
#define FL_Q 0
#define FL_K 16384
#define FL_V 32768
#define FL_M 49152
#define FL_SMEM 57344
#define BKV 64
#define NIT (Sq / BKV)   // 32

__global__ __launch_bounds__(256, 2)
void flash_k(const __nv_bfloat16* __restrict__ Qg, const __nv_bfloat16* __restrict__ Kg,
             const __nv_bfloat16* __restrict__ Vt, const float* __restrict__ mask,
             __nv_bfloat16* __restrict__ ctx) {
    extern __shared__ char smem[];
    const uint32_t sb = smem_to_u32(smem);

    const int tid  = threadIdx.x;
    const int wid  = tid >> 5;
    const int lane = tid & 31;
    const int m0   = blockIdx.x * 128;
    const int bz   = blockIdx.y;
    const int bb   = bz >> 4, hh = bz & 15;

    const __nv_bfloat16* Qb = Qg + ((size_t)bz * Sq + m0) * HDq;
    const __nv_bfloat16* Kb = Kg + (size_t)bz * Sq * HDq;
    const __nv_bfloat16* Vb = Vt + (size_t)bz * HDq * Sq;
    const float* mrow = mask + (size_t)bb * Sq;

#pragma unroll
    for (int i = 0; i < 4; ++i) {
        const int idx = tid + i * 256, r = idx >> 3, c = idx & 7;
        cp_async16(sb + FL_Q + r * 128 + ((c * 16) ^ ((r & 7) << 4)),
                   Qb + (size_t)r * HDq + c * 8);
    }
#pragma unroll
    for (int i = 0; i < 2; ++i) {
        const int idx = tid + i * 256;
        cp_async16(sb + FL_M + idx * 16, mrow + idx * 4);
    }

    auto issue_kv = [&](int it) {
        const uint32_t sK = sb + FL_K + (uint32_t)(it & 1) * 8192;
        const __nv_bfloat16* Ks = Kb + (size_t)it * BKV * HDq;
#pragma unroll
        for (int i = 0; i < 2; ++i) {
            const int idx = tid + i * 256, r = idx >> 3, c = idx & 7;
            cp_async16(sK + r * 128 + ((c * 16) ^ ((r & 7) << 4)),
                       Ks + (size_t)r * HDq + c * 8);
        }
        const uint32_t sV = sb + FL_V + (uint32_t)(it & 1) * 8192;
        const __nv_bfloat16* Vs = Vb + (size_t)it * BKV;
#pragma unroll
        for (int i = 0; i < 2; ++i) {
            const int idx = tid + i * 256, d = idx >> 3, c = idx & 7;
            cp_async16(sV + d * 128 + ((c * 16) ^ ((d & 7) << 4)),
                       Vs + (size_t)d * Sq + c * 8);
        }
    };

    issue_kv(0);
    cp_commit();

    const int mat = lane >> 3, mr = lane & 7;
    const int aro = (mat & 1) * 8 + mr;
    const int ako = (mat >> 1) * 16;
    const int bro = (mat >> 1) * 8 + mr;
    const int bko = (mat & 1) * 16;
    const int g   = lane >> 2, tig = lane & 3;

    asm volatile("cp.async.wait_group 0;" ::: "memory");
    __syncthreads();

    uint32_t qf[4][4];
#pragma unroll
    for (int ks = 0; ks < 4; ++ks) {
        const int row = wid * 16 + aro;
        const int kb  = ks * 32 + ako;
        ldsm4(qf[ks][0], qf[ks][1], qf[ks][2], qf[ks][3],
              sb + FL_Q + row * 128 + (kb ^ ((row & 7) << 4)));
    }

    float accO[8][4];
#pragma unroll
    for (int nt = 0; nt < 8; ++nt)
#pragma unroll
        for (int e = 0; e < 4; ++e) accO[nt][e] = 0.0f;
    float mst[2] = {-CUDART_INF_F, -CUDART_INF_F};
    float lst[2] = {0.0f, 0.0f};

    for (int it = 0; it < NIT; ++it) {
        if (it) {
            asm volatile("cp.async.wait_group 0;" ::: "memory");
            __syncthreads();
        }
        if (it + 1 < NIT) {
            issue_kv(it + 1);
            cp_commit();
        }

        const uint32_t sK = sb + FL_K + (uint32_t)(it & 1) * 8192;
        const uint32_t sV = sb + FL_V + (uint32_t)(it & 1) * 8192;

        float accS[8][4];
#pragma unroll
        for (int nt = 0; nt < 8; ++nt)
#pragma unroll
            for (int e = 0; e < 4; ++e) accS[nt][e] = 0.0f;
#pragma unroll
        for (int ks = 0; ks < 4; ++ks) {
            uint32_t bf[8][2];
            const int kb = ks * 32 + bko;
#pragma unroll
            for (int np = 0; np < 4; ++np) {
                const int row = np * 16 + bro;
                ldsm4(bf[2 * np][0], bf[2 * np][1], bf[2 * np + 1][0], bf[2 * np + 1][1],
                      sK + row * 128 + (kb ^ ((row & 7) << 4)));
            }
#pragma unroll
            for (int nt = 0; nt < 8; ++nt)
                mma_bf16(accS[nt], qf[ks], bf[nt]);
        }

#pragma unroll
        for (int nt = 0; nt < 8; ++nt) {
            const float2 mk = *reinterpret_cast<const float2*>(
                smem + FL_M + (it * BKV + nt * 8 + 2 * tig) * 4);
            accS[nt][0] += mk.x; accS[nt][1] += mk.y;
            accS[nt][2] += mk.x; accS[nt][3] += mk.y;
        }

        float rmax[2] = {-CUDART_INF_F, -CUDART_INF_F};
#pragma unroll
        for (int nt = 0; nt < 8; ++nt) {
            rmax[0] = fmaxf(rmax[0], fmaxf(accS[nt][0], accS[nt][1]));
            rmax[1] = fmaxf(rmax[1], fmaxf(accS[nt][2], accS[nt][3]));
        }
#pragma unroll
        for (int h = 0; h < 2; ++h) {
            rmax[h] = fmaxf(rmax[h], __shfl_xor_sync(0xffffffffu, rmax[h], 1));
            rmax[h] = fmaxf(rmax[h], __shfl_xor_sync(0xffffffffu, rmax[h], 2));
        }
        float scl[2], rsum[2] = {0.0f, 0.0f};
#pragma unroll
        for (int h = 0; h < 2; ++h) {
            const float mnew = fmaxf(mst[h], rmax[h]);
            scl[h] = __expf(mst[h] - mnew);
            mst[h] = mnew;
        }
#pragma unroll
        for (int nt = 0; nt < 8; ++nt) {
            accS[nt][0] = __expf(accS[nt][0] - mst[0]);
            accS[nt][1] = __expf(accS[nt][1] - mst[0]);
            accS[nt][2] = __expf(accS[nt][2] - mst[1]);
            accS[nt][3] = __expf(accS[nt][3] - mst[1]);
            rsum[0] += accS[nt][0] + accS[nt][1];
            rsum[1] += accS[nt][2] + accS[nt][3];
        }
#pragma unroll
        for (int h = 0; h < 2; ++h) {
            rsum[h] += __shfl_xor_sync(0xffffffffu, rsum[h], 1);
            rsum[h] += __shfl_xor_sync(0xffffffffu, rsum[h], 2);
            lst[h] = lst[h] * scl[h] + rsum[h];
        }
#pragma unroll
        for (int nt = 0; nt < 8; ++nt) {
            accO[nt][0] *= scl[0]; accO[nt][1] *= scl[0];
            accO[nt][2] *= scl[1]; accO[nt][3] *= scl[1];
        }

        uint32_t af[4][4];
#pragma unroll
        for (int k2 = 0; k2 < 4; ++k2) {
            af[k2][0] = packbf(accS[2 * k2][0],     accS[2 * k2][1]);
            af[k2][1] = packbf(accS[2 * k2][2],     accS[2 * k2][3]);
            af[k2][2] = packbf(accS[2 * k2 + 1][0], accS[2 * k2 + 1][1]);
            af[k2][3] = packbf(accS[2 * k2 + 1][2], accS[2 * k2 + 1][3]);
        }

#pragma unroll
        for (int ks = 0; ks < 4; ++ks) {
            uint32_t bf[8][2];
            const int kb = ks * 32 + bko;
#pragma unroll
            for (int np = 0; np < 4; ++np) {
                const int row = np * 16 + bro;
                ldsm4(bf[2 * np][0], bf[2 * np][1], bf[2 * np + 1][0], bf[2 * np + 1][1],
                      sV + row * 128 + (kb ^ ((row & 7) << 4)));
            }
#pragma unroll
            for (int nt = 0; nt < 8; ++nt)
                mma_bf16(accO[nt], af[ks], bf[nt]);
        }
    }

#pragma unroll
    for (int h = 0; h < 2; ++h) {
        const int sI = m0 + wid * 16 + g + 8 * h;
        __nv_bfloat16* crow = ctx + ((size_t)bb * Sq + sI) * Hq + hh * HDq;
        const float inv = 1.0f / lst[h];
#pragma unroll
        for (int nt = 0; nt < 8; ++nt) {
            const int d = nt * 8 + 2 * tig;
            *reinterpret_cast<__nv_bfloat162*>(crow + d) =
                __floats2bfloat162_rn(accO[nt][2 * h + 0] * inv,
                                      accO[nt][2 * h + 1] * inv);
        }
    }
}

// ---------------------------------------------------------------------------
// Launch
// ---------------------------------------------------------------------------
extern "C" void kernel_launch(void* const* d_in, const int* in_sizes, int n_in,
                              void* d_out, int out_size) {
    const float* hs   = (const float*)d_in[0];
    const float* mask = (const float*)d_in[1];
    const float* wq   = (const float*)d_in[2];
    const float* bq   = (const float*)d_in[3];
    const float* wk   = (const float*)d_in[4];
    const float* bk   = (const float*)d_in[5];
    const float* wv   = (const float*)d_in[6];
    const float* bv   = (const float*)d_in[7];
    const float* wo   = (const float*)d_in[8];
    const float* bo   = (const float*)d_in[9];
    const float* gam  = (const float*)d_in[10];
    const float* bet  = (const float*)d_in[11];
    float* out = (float*)d_out;

    __nv_bfloat16 *xln, *bwqkv, *bwo, *q, *k, *v, *ctx;
    cudaGetSymbolAddress((void**)&xln,   g_xln);
    cudaGetSymbolAddress((void**)&bwqkv, g_wqkv);
    cudaGetSymbolAddress((void**)&bwo,   g_wo);
    cudaGetSymbolAddress((void**)&q,     g_q);
    cudaGetSymbolAddress((void**)&k,     g_k);
    cudaGetSymbolAddress((void**)&v,     g_v);
    cudaGetSymbolAddress((void**)&ctx,   g_ctx);

    constexpr int SMW = 3 * (128 * 128 + 128 * 128);  // 98304
    cudaFuncSetAttribute((const void*)wmma_k<0>, cudaFuncAttributeMaxDynamicSharedMemorySize, SMW);
    cudaFuncSetAttribute((const void*)wmma_k<5>, cudaFuncAttributeMaxDynamicSharedMemorySize, SMW);
    cudaFuncSetAttribute((const void*)flash_k, cudaFuncAttributeMaxDynamicSharedMemorySize, FL_SMEM);

    // 0) all weight conversions, one launch (wq/wk/wv packed into g_wqkv)
    constexpr int N4 = Hq * Hq / 4;
    cvt4_k<<<dim3((N4 + 255) / 256, 4), 256>>>(
        (const float4*)wq, (const float4*)wk, (const float4*)wv, (const float4*)wo,
        (__nv_bfloat162*)bwqkv, (__nv_bfloat162*)bwo, N4);

    // 1) LayerNorm -> bf16
    ln_k<<<Mq, 256>>>(hs, gam, bet, xln);

    // 2) merged QKV projection (N=3072); Q pre-scaled, V transposed
    wmma_k<5><<<dim3(3 * Hq / 128, Mq / 128), 256, SMW>>>(
        xln, bwqkv, bq, bk, bv, nullptr, q, k, v, Hq);

    // 3) flash attention -> ctx (bf16)
    flash_k<<<dim3(Sq / 128, Bq * NHq), 256, FL_SMEM>>>(q, k, v, mask, ctx);

    // 4) out = ctx Wo^T + bo + residual (fp32 out)
    wmma_k<0><<<dim3(Hq / 128, Mq / 128), 256, SMW>>>(
        ctx, bwo, bo, nullptr, nullptr, hs, out, nullptr, nullptr, Hq);
}